// round 4
// baseline (speedup 1.0000x reference)
#include <cuda_runtime.h>
#include <cuda_bf16.h>
#include <math.h>

// ---------------------------------------------------------------------------
// Problem constants
// ---------------------------------------------------------------------------
#define T_TOK   6400
#define D_DIM   512
#define HID     1024
#define N_SEQ   2048
#define EPS     1e-6f
#define INV_N   (1.0f/2048.0f)

__device__ __constant__ int c_off[5] = {0, 2048, 3584, 4608, 6400};
// (batch, qt) pairs for 128-row q-tiles, sorted by qt descending (load balance)
__device__ __constant__ unsigned char c_ord[50][2] = {
 {0,15},{0,14},{0,13},{3,13},{0,12},{3,12},{0,11},{1,11},{3,11},{0,10},
 {1,10},{3,10},{0,9},{1,9},{3,9},{0,8},{1,8},{3,8},{0,7},{1,7},
 {2,7},{3,7},{0,6},{1,6},{2,6},{3,6},{0,5},{1,5},{2,5},{3,5},
 {0,4},{1,4},{2,4},{3,4},{0,3},{1,3},{2,3},{3,3},{0,2},{1,2},
 {2,2},{3,2},{0,1},{1,1},{2,1},{3,1},{0,0},{1,0},{2,0},{3,0}};

// ---------------------------------------------------------------------------
// Scratch
// ---------------------------------------------------------------------------
__device__ float g_xn  [T_TOK * D_DIM];
__device__ float g_h   [T_TOK * HID];     // u|v|q|k
__device__ float g_attn[T_TOK * 256];
__device__ float g_oin [T_TOK * 256];

// ---------------------------------------------------------------------------
// helpers
// ---------------------------------------------------------------------------
__device__ __forceinline__ unsigned f2tf(float x) {
    unsigned u; asm("cvt.rna.tf32.f32 %0, %1;" : "=r"(u) : "f"(x)); return u;
}
__device__ __forceinline__ void mma8(float* c, const unsigned* a, const unsigned* b) {
    asm volatile(
      "mma.sync.aligned.m16n8k8.row.col.f32.tf32.tf32.f32 "
      "{%0,%1,%2,%3}, {%4,%5,%6,%7}, {%8,%9}, {%0,%1,%2,%3};"
      : "+f"(c[0]), "+f"(c[1]), "+f"(c[2]), "+f"(c[3])
      : "r"(a[0]), "r"(a[1]), "r"(a[2]), "r"(a[3]), "r"(b[0]), "r"(b[1]));
}
__device__ __forceinline__ float silu_f(float s) {
    return s * __fdividef(1.0f, 1.0f + __expf(-s));
}

// ---------------------------------------------------------------------------
// Kernel 1: LayerNorm over D=512, warp-per-token
// ---------------------------------------------------------------------------
__global__ void ln_x_kernel(const float* __restrict__ x) {
    int t = blockIdx.x * 8 + (threadIdx.x >> 5);
    int lane = threadIdx.x & 31;
    const float* row = x + (size_t)t * D_DIM + lane * 4;
    float4 v[4];
    #pragma unroll
    for (int w = 0; w < 4; w++) v[w] = *(const float4*)(row + w * 128);
    float s = 0.f, q = 0.f;
    #pragma unroll
    for (int w = 0; w < 4; w++) {
        s += v[w].x + v[w].y + v[w].z + v[w].w;
        q += v[w].x*v[w].x + v[w].y*v[w].y + v[w].z*v[w].z + v[w].w*v[w].w;
    }
    #pragma unroll
    for (int o = 16; o > 0; o >>= 1) {
        s += __shfl_xor_sync(0xffffffffu, s, o);
        q += __shfl_xor_sync(0xffffffffu, q, o);
    }
    float m = s * (1.0f / D_DIM);
    float r = rsqrtf(q * (1.0f / D_DIM) - m * m + EPS);
    float* dst = g_xn + (size_t)t * D_DIM + lane * 4;
    #pragma unroll
    for (int w = 0; w < 4; w++) {
        *(float4*)(dst + w * 128) = make_float4(
            (v[w].x - m) * r, (v[w].y - m) * r, (v[w].z - m) * r, (v[w].w - m) * r);
    }
}

// ---------------------------------------------------------------------------
// Kernel 2: h = silu(xn @ uvqk)  -- tf32 mma, BM=128 BN=64 BK=32
// ---------------------------------------------------------------------------
__global__ void gemm_uvqk_mma(const float* __restrict__ W) {
    __shared__ unsigned As[128 * 36];
    __shared__ unsigned Bs[32 * 72];
    int tid = threadIdx.x, lane = tid & 31, warp = tid >> 5;
    int wm = warp >> 1, wn = warp & 1;
    int m0 = blockIdx.y * 128, n0 = blockIdx.x * 64;

    float acc[2][4][4];
    #pragma unroll
    for (int a = 0; a < 2; a++)
        #pragma unroll
        for (int b = 0; b < 4; b++)
            #pragma unroll
            for (int c = 0; c < 4; c++) acc[a][b][c] = 0.f;

    int lr = tid >> 1, lk = (tid & 1) << 4;
    int bk = tid >> 3, bn = (tid & 7) << 3;
    const float* Ap = g_xn + (size_t)(m0 + lr) * D_DIM + lk;

    for (int k0 = 0; k0 < D_DIM; k0 += 32) {
        float4 av[4];
        #pragma unroll
        for (int j = 0; j < 4; j++) av[j] = *(const float4*)(Ap + k0 + 4 * j);
        float4 b0 = *(const float4*)&W[(size_t)(k0 + bk) * HID + n0 + bn];
        float4 b1 = *(const float4*)&W[(size_t)(k0 + bk) * HID + n0 + bn + 4];
        __syncthreads();
        #pragma unroll
        for (int j = 0; j < 4; j++) {
            As[lr * 36 + lk + 4*j + 0] = f2tf(av[j].x);
            As[lr * 36 + lk + 4*j + 1] = f2tf(av[j].y);
            As[lr * 36 + lk + 4*j + 2] = f2tf(av[j].z);
            As[lr * 36 + lk + 4*j + 3] = f2tf(av[j].w);
        }
        Bs[bk * 72 + bn + 0] = f2tf(b0.x); Bs[bk * 72 + bn + 1] = f2tf(b0.y);
        Bs[bk * 72 + bn + 2] = f2tf(b0.z); Bs[bk * 72 + bn + 3] = f2tf(b0.w);
        Bs[bk * 72 + bn + 4] = f2tf(b1.x); Bs[bk * 72 + bn + 5] = f2tf(b1.y);
        Bs[bk * 72 + bn + 6] = f2tf(b1.z); Bs[bk * 72 + bn + 7] = f2tf(b1.w);
        __syncthreads();
        #pragma unroll
        for (int ks = 0; ks < 4; ks++) {
            int kk = ks * 8 + (lane & 3);
            unsigned af[2][4];
            #pragma unroll
            for (int mm = 0; mm < 2; mm++) {
                int r = wm * 32 + mm * 16 + (lane >> 2);
                af[mm][0] = As[r * 36 + kk];
                af[mm][1] = As[(r + 8) * 36 + kk];
                af[mm][2] = As[r * 36 + kk + 4];
                af[mm][3] = As[(r + 8) * 36 + kk + 4];
            }
            #pragma unroll
            for (int nm = 0; nm < 4; nm++) {
                int cn = wn * 32 + nm * 8 + (lane >> 2);
                unsigned bf[2] = { Bs[kk * 72 + cn], Bs[(kk + 4) * 72 + cn] };
                mma8(acc[0][nm], af[0], bf);
                mma8(acc[1][nm], af[1], bf);
            }
        }
    }
    #pragma unroll
    for (int mm = 0; mm < 2; mm++) {
        #pragma unroll
        for (int nm = 0; nm < 4; nm++) {
            int r = m0 + wm * 32 + mm * 16 + (lane >> 2);
            int c = n0 + wn * 32 + nm * 8 + 2 * (lane & 3);
            *(float2*)&g_h[(size_t)r * HID + c] =
                make_float2(silu_f(acc[mm][nm][0]), silu_f(acc[mm][nm][1]));
            *(float2*)&g_h[(size_t)(r + 8) * HID + c] =
                make_float2(silu_f(acc[mm][nm][2]), silu_f(acc[mm][nm][3]));
        }
    }
}

// ---------------------------------------------------------------------------
// Kernel 3: jagged causal attention, 128-row q-tiles, tf32 mma
// S^T[64j][128i] = K Q^T ; P^T -> SMEM ; O[128i][64l] += P V
// ---------------------------------------------------------------------------
#define A_QS 0
#define A_KS (64 * 136)
#define A_VS (A_KS + 64 * 68)
#define A_PS (A_VS + 64 * 72)
#define A_AUX (A_PS + 64 * 136)
#define ATTN_WORDS (A_AUX + 132 + 16 + 128 + 64)
#define SMEM_ATTN (ATTN_WORDS * 4)

__global__ void __launch_bounds__(256, 2)
attn_mma(const int* __restrict__ ts, const float* __restrict__ tsw) {
    extern __shared__ unsigned sm[];
    unsigned* Qs = sm + A_QS;   // [d=64][i=128] stride 136
    unsigned* Ks = sm + A_KS;   // [j=64][d=64] stride 68
    unsigned* Vs = sm + A_VS;   // [j=64][l=64] stride 72
    unsigned* Ps = sm + A_PS;   // [j=64][i=128] stride 136
    float* tw  = (float*)(sm + A_AUX);  // 129 (pad 132)
    float* thf = tw + 132;              // 16
    int* tqs = (int*)(thf + 16);        // 128
    int* tks = tqs + 128;               // 64

    int b  = c_ord[blockIdx.x][0];
    int qt = c_ord[blockIdx.x][1];
    int head = blockIdx.y;
    int tok0 = c_off[b] + qt * 128;

    int tid = threadIdx.x, lane = tid & 31, warp = tid >> 5;
    int wmS = warp >> 2, wnS = warp & 3;   // S-phase: 2x4 (j x i)
    int wmO = warp >> 1, wnO = warp & 1;   // O-phase: 4x2 (i x l)

    // stage Q transposed (once per block): 128 rows x 64 d
    const float* qb = g_h + 512 + head * 64;
    for (int i = tid; i < 2048; i += 256) {
        int r = i >> 4, c = (i & 15) << 2;
        float4 v = *(const float4*)&qb[(size_t)(tok0 + r) * HID + c];
        Qs[(c + 0) * 136 + r] = f2tf(v.x);
        Qs[(c + 1) * 136 + r] = f2tf(v.y);
        Qs[(c + 2) * 136 + r] = f2tf(v.z);
        Qs[(c + 3) * 136 + r] = f2tf(v.w);
    }
    for (int i = tid; i < 129; i += 256) tw[i] = tsw[i];
    if (tid < 128) tqs[tid] = ts[b * N_SEQ + qt * 128 + tid];
    if (tid < 15) {
        if (tid == 0) thf[0] = 0.f;
        else {
            int k = tid;
            int t = (int)(expf((float)k)) - 9;
            if (t < 1) t = 1;
            while (t > 1 && log1pf((float)(t - 1)) >= (float)k) --t;
            while (log1pf((float)t) < (float)k) ++t;
            thf[k] = (float)t;
        }
    }
    __syncthreads();
    float th[14];
    #pragma unroll
    for (int k = 0; k < 14; k++) th[k] = thf[k + 1];

    float accO[2][4][4];
    #pragma unroll
    for (int a = 0; a < 2; a++)
        #pragma unroll
        for (int n = 0; n < 4; n++)
            #pragma unroll
            for (int c = 0; c < 4; c++) accO[a][n][c] = 0.f;

    const float* kb = g_h + 768 + head * 64;
    const float* vb = g_h + 256 + head * 64;
    int jmax = 2 * qt + 1;

    for (int jt = 0; jt <= jmax; ++jt) {
        int ktok = c_off[b] + jt * 64;
        // hoisted global loads (overlap with previous O-phase)
        float4 kreg[4], vreg[4];
        int rr[4], cc[4];
        #pragma unroll
        for (int it = 0; it < 4; it++) {
            int i = tid + it * 256;
            rr[it] = i >> 4; cc[it] = (i & 15) << 2;
            kreg[it] = *(const float4*)&kb[(size_t)(ktok + rr[it]) * HID + cc[it]];
            vreg[it] = *(const float4*)&vb[(size_t)(ktok + rr[it]) * HID + cc[it]];
        }
        int tkv = (tid < 64) ? ts[b * N_SEQ + jt * 64 + tid] : 0;
        __syncthreads();   // previous O-phase done with Vs/Ps
        #pragma unroll
        for (int it = 0; it < 4; it++) {
            *(uint4*)&Ks[rr[it] * 68 + cc[it]] = make_uint4(
                f2tf(kreg[it].x), f2tf(kreg[it].y), f2tf(kreg[it].z), f2tf(kreg[it].w));
            *(uint4*)&Vs[rr[it] * 72 + cc[it]] = make_uint4(
                f2tf(vreg[it].x), f2tf(vreg[it].y), f2tf(vreg[it].z), f2tf(vreg[it].w));
        }
        if (tid < 64) tks[tid] = tkv;
        __syncthreads();

        // S^T[j][i] = sum_d K[j][d] Q[i][d]
        float accS[2][4][4];
        #pragma unroll
        for (int a = 0; a < 2; a++)
            #pragma unroll
            for (int n = 0; n < 4; n++)
                #pragma unroll
                for (int c = 0; c < 4; c++) accS[a][n][c] = 0.f;
        #pragma unroll
        for (int kc = 0; kc < 8; kc++) {
            int kk = kc * 8 + (lane & 3);
            unsigned af[2][4];
            #pragma unroll
            for (int mm = 0; mm < 2; mm++) {
                int jr = wmS * 32 + mm * 16 + (lane >> 2);
                af[mm][0] = Ks[jr * 68 + kk];
                af[mm][1] = Ks[(jr + 8) * 68 + kk];
                af[mm][2] = Ks[jr * 68 + kk + 4];
                af[mm][3] = Ks[(jr + 8) * 68 + kk + 4];
            }
            #pragma unroll
            for (int nm = 0; nm < 4; nm++) {
                int ic = wnS * 32 + nm * 8 + (lane >> 2);
                unsigned bf[2] = { Qs[kk * 136 + ic], Qs[(kk + 4) * 136 + ic] };
                mma8(accS[0][nm], af[0], bf);
                mma8(accS[1][nm], af[1], bf);
            }
        }

        // epilogue: bias + silu + causal -> Ps (transposed [j][i])
        bool full = (jt < 2 * qt);
        int jo = jt * 64 - qt * 128;   // j_local + jo <= i_local for validity
        #pragma unroll
        for (int mm = 0; mm < 2; mm++) {
            #pragma unroll
            for (int nm = 0; nm < 4; nm++) {
                #pragma unroll
                for (int e = 0; e < 4; e++) {
                    int j = wmS * 32 + mm * 16 + (lane >> 2) + ((e & 2) ? 8 : 0);
                    int i = wnS * 32 + nm * 8 + 2 * (lane & 3) + (e & 1);
                    float p = 0.f;
                    if (full || (jo + j) <= i) {
                        float fd = fabsf((float)(tqs[i] - tks[j]));
                        int bkt = 0;
                        #pragma unroll
                        for (int k = 0; k < 14; k++) bkt += (fd >= th[k]) ? 1 : 0;
                        float s = accS[mm][nm][e] + tw[bkt];
                        p = silu_f(s) * INV_N;
                    }
                    Ps[j * 136 + i] = f2tf(p);
                }
            }
        }
        __syncthreads();

        // O[i][l] += sum_j P[i][j] V[j][l]
        #pragma unroll
        for (int kc = 0; kc < 8; kc++) {
            int kk = kc * 8 + (lane & 3);
            unsigned af[2][4];
            #pragma unroll
            for (int mm = 0; mm < 2; mm++) {
                int ir = wmO * 32 + mm * 16 + (lane >> 2);
                af[mm][0] = Ps[kk * 136 + ir];
                af[mm][1] = Ps[kk * 136 + ir + 8];
                af[mm][2] = Ps[(kk + 4) * 136 + ir];
                af[mm][3] = Ps[(kk + 4) * 136 + ir + 8];
            }
            #pragma unroll
            for (int nm = 0; nm < 4; nm++) {
                int lc = wnO * 32 + nm * 8 + (lane >> 2);
                unsigned bf[2] = { Vs[kk * 72 + lc], Vs[(kk + 4) * 72 + lc] };
                mma8(accO[0][nm], af[0], bf);
                mma8(accO[1][nm], af[1], bf);
            }
        }
    }

    #pragma unroll
    for (int mm = 0; mm < 2; mm++) {
        #pragma unroll
        for (int nm = 0; nm < 4; nm++) {
            int i = wmO * 32 + mm * 16 + (lane >> 2);
            int l = wnO * 32 + nm * 8 + 2 * (lane & 3);
            *(float2*)&g_attn[(size_t)(tok0 + i) * 256 + head * 64 + l] =
                make_float2(accO[mm][nm][0], accO[mm][nm][1]);
            *(float2*)&g_attn[(size_t)(tok0 + i + 8) * 256 + head * 64 + l] =
                make_float2(accO[mm][nm][2], accO[mm][nm][3]);
        }
    }
}

// ---------------------------------------------------------------------------
// Kernel 4: oin = u * LN(attn), warp-per-token
// ---------------------------------------------------------------------------
__global__ void oin_kernel() {
    int t = blockIdx.x * 8 + (threadIdx.x >> 5);
    int lane = threadIdx.x & 31;
    const float* row = g_attn + (size_t)t * 256 + lane * 4;
    float4 a0 = *(const float4*)(row);
    float4 a1 = *(const float4*)(row + 128);
    float s = a0.x + a0.y + a0.z + a0.w + a1.x + a1.y + a1.z + a1.w;
    float q = a0.x*a0.x + a0.y*a0.y + a0.z*a0.z + a0.w*a0.w
            + a1.x*a1.x + a1.y*a1.y + a1.z*a1.z + a1.w*a1.w;
    #pragma unroll
    for (int o = 16; o > 0; o >>= 1) {
        s += __shfl_xor_sync(0xffffffffu, s, o);
        q += __shfl_xor_sync(0xffffffffu, q, o);
    }
    float m = s * (1.0f / 256.0f);
    float r = rsqrtf(q * (1.0f / 256.0f) - m * m + EPS);
    const float* up = g_h + (size_t)t * HID + lane * 4;
    float4 u0 = *(const float4*)(up);
    float4 u1 = *(const float4*)(up + 128);
    float* dst = g_oin + (size_t)t * 256 + lane * 4;
    *(float4*)(dst) = make_float4(u0.x * (a0.x - m) * r, u0.y * (a0.y - m) * r,
                                  u0.z * (a0.z - m) * r, u0.w * (a0.w - m) * r);
    *(float4*)(dst + 128) = make_float4(u1.x * (a1.x - m) * r, u1.y * (a1.y - m) * r,
                                        u1.z * (a1.z - m) * r, u1.w * (a1.w - m) * r);
}

// ---------------------------------------------------------------------------
// Kernel 5: out = oin @ o_w^T + o_b + x  -- tf32 mma, BK=32
// ---------------------------------------------------------------------------
__global__ void gemm_out_mma(const float* __restrict__ Wo,    // [512,256]
                             const float* __restrict__ bias,  // [512]
                             const float* __restrict__ x,
                             float* __restrict__ out) {
    __shared__ unsigned As[128 * 36];
    __shared__ unsigned Bs[32 * 72];
    int tid = threadIdx.x, lane = tid & 31, warp = tid >> 5;
    int wm = warp >> 1, wn = warp & 1;
    int m0 = blockIdx.y * 128, n0 = blockIdx.x * 64;

    float acc[2][4][4];
    #pragma unroll
    for (int a = 0; a < 2; a++)
        #pragma unroll
        for (int b = 0; b < 4; b++)
            #pragma unroll
            for (int c = 0; c < 4; c++) acc[a][b][c] = 0.f;

    int lr = tid >> 1, lk = (tid & 1) << 4;
    int bn = tid & 63, bk = (tid >> 6) << 3;

    for (int k0 = 0; k0 < 256; k0 += 32) {
        float4 av[4];
        #pragma unroll
        for (int j = 0; j < 4; j++)
            av[j] = *(const float4*)&g_oin[(size_t)(m0 + lr) * 256 + k0 + lk + 4*j];
        float4 w0 = *(const float4*)&Wo[(size_t)(n0 + bn) * 256 + k0 + bk];
        float4 w1 = *(const float4*)&Wo[(size_t)(n0 + bn) * 256 + k0 + bk + 4];
        __syncthreads();
        #pragma unroll
        for (int j = 0; j < 4; j++) {
            As[lr * 36 + lk + 4*j + 0] = f2tf(av[j].x);
            As[lr * 36 + lk + 4*j + 1] = f2tf(av[j].y);
            As[lr * 36 + lk + 4*j + 2] = f2tf(av[j].z);
            As[lr * 36 + lk + 4*j + 3] = f2tf(av[j].w);
        }
        Bs[(bk + 0) * 72 + bn] = f2tf(w0.x); Bs[(bk + 1) * 72 + bn] = f2tf(w0.y);
        Bs[(bk + 2) * 72 + bn] = f2tf(w0.z); Bs[(bk + 3) * 72 + bn] = f2tf(w0.w);
        Bs[(bk + 4) * 72 + bn] = f2tf(w1.x); Bs[(bk + 5) * 72 + bn] = f2tf(w1.y);
        Bs[(bk + 6) * 72 + bn] = f2tf(w1.z); Bs[(bk + 7) * 72 + bn] = f2tf(w1.w);
        __syncthreads();
        #pragma unroll
        for (int ks = 0; ks < 4; ks++) {
            int kk = ks * 8 + (lane & 3);
            unsigned af[2][4];
            #pragma unroll
            for (int mm = 0; mm < 2; mm++) {
                int r = wm * 32 + mm * 16 + (lane >> 2);
                af[mm][0] = As[r * 36 + kk];
                af[mm][1] = As[(r + 8) * 36 + kk];
                af[mm][2] = As[r * 36 + kk + 4];
                af[mm][3] = As[(r + 8) * 36 + kk + 4];
            }
            #pragma unroll
            for (int nm = 0; nm < 4; nm++) {
                int cn = wn * 32 + nm * 8 + (lane >> 2);
                unsigned bf[2] = { Bs[kk * 72 + cn], Bs[(kk + 4) * 72 + cn] };
                mma8(acc[0][nm], af[0], bf);
                mma8(acc[1][nm], af[1], bf);
            }
        }
    }
    #pragma unroll
    for (int mm = 0; mm < 2; mm++) {
        #pragma unroll
        for (int nm = 0; nm < 4; nm++) {
            int r = m0 + wm * 32 + mm * 16 + (lane >> 2);
            int c = n0 + wn * 32 + nm * 8 + 2 * (lane & 3);
            float2 xr0 = *(const float2*)&x[(size_t)r * D_DIM + c];
            float2 xr1 = *(const float2*)&x[(size_t)(r + 8) * D_DIM + c];
            float b0 = bias[c], b1 = bias[c + 1];
            *(float2*)&out[(size_t)r * D_DIM + c] =
                make_float2(acc[mm][nm][0] + b0 + xr0.x, acc[mm][nm][1] + b1 + xr0.y);
            *(float2*)&out[(size_t)(r + 8) * D_DIM + c] =
                make_float2(acc[mm][nm][2] + b0 + xr1.x, acc[mm][nm][3] + b1 + xr1.y);
        }
    }
}

// ---------------------------------------------------------------------------
// Launcher
// ---------------------------------------------------------------------------
extern "C" void kernel_launch(void* const* d_in, const int* in_sizes, int n_in,
                              void* d_out, int out_size) {
    const float* x    = (const float*)d_in[0];
    const float* uvqk = (const float*)d_in[1];
    const float* o_w  = (const float*)d_in[2];
    const float* o_b  = (const float*)d_in[3];
    const float* ts_w = (const float*)d_in[4];
    const int*   ts   = (const int*)d_in[5];
    float* out = (float*)d_out;

    ln_x_kernel<<<T_TOK / 8, 256>>>(x);
    gemm_uvqk_mma<<<dim3(HID / 64, T_TOK / 128), 256>>>(uvqk);

    cudaFuncSetAttribute(attn_mma,
                         cudaFuncAttributeMaxDynamicSharedMemorySize, SMEM_ATTN);
    attn_mma<<<dim3(50, 4), 256, SMEM_ATTN>>>(ts, ts_w);

    oin_kernel<<<T_TOK / 8, 256>>>();
    gemm_out_mma<<<dim3(D_DIM / 64, T_TOK / 128), 256>>>(o_w, o_b, x, out);
}

// round 7
// speedup vs baseline: 1.3071x; 1.3071x over previous
#include <cuda_runtime.h>
#include <cuda_bf16.h>
#include <math.h>

// ---------------------------------------------------------------------------
// Problem constants
// ---------------------------------------------------------------------------
#define T_TOK   6400
#define D_DIM   512
#define HID     1024
#define N_SEQ   2048
#define EPS     1e-6f
#define INV_N   (1.0f/2048.0f)

__device__ __constant__ int c_off[5] = {0, 2048, 3584, 4608, 6400};
// (batch, qt) for 64-row q-tiles, exact qt-descending order (longest first).
// counts: b0=32 (qt0..31), b1=24, b2=16, b3=28
__device__ __constant__ unsigned char c_ord[100][2] = {
 {0,31},{0,30},{0,29},{0,28},
 {0,27},{3,27},{0,26},{3,26},{0,25},{3,25},{0,24},{3,24},
 {0,23},{1,23},{3,23},{0,22},{1,22},{3,22},{0,21},{1,21},{3,21},
 {0,20},{1,20},{3,20},{0,19},{1,19},{3,19},{0,18},{1,18},{3,18},
 {0,17},{1,17},{3,17},{0,16},{1,16},{3,16},
 {0,15},{1,15},{2,15},{3,15},{0,14},{1,14},{2,14},{3,14},
 {0,13},{1,13},{2,13},{3,13},{0,12},{1,12},{2,12},{3,12},
 {0,11},{1,11},{2,11},{3,11},{0,10},{1,10},{2,10},{3,10},
 {0,9},{1,9},{2,9},{3,9},{0,8},{1,8},{2,8},{3,8},
 {0,7},{1,7},{2,7},{3,7},{0,6},{1,6},{2,6},{3,6},
 {0,5},{1,5},{2,5},{3,5},{0,4},{1,4},{2,4},{3,4},
 {0,3},{1,3},{2,3},{3,3},{0,2},{1,2},{2,2},{3,2},
 {0,1},{1,1},{2,1},{3,1},{0,0},{1,0},{2,0},{3,0}};

// ---------------------------------------------------------------------------
// Scratch
// ---------------------------------------------------------------------------
__device__ float g_xn  [T_TOK * D_DIM];
__device__ float g_h   [T_TOK * HID];     // u|v|q|k
__device__ float g_attn[T_TOK * 256];
__device__ float g_oin [T_TOK * 256];

// ---------------------------------------------------------------------------
// helpers
// ---------------------------------------------------------------------------
__device__ __forceinline__ unsigned f2tf(float x) {
    unsigned u; asm("cvt.rna.tf32.f32 %0, %1;" : "=r"(u) : "f"(x)); return u;
}
__device__ __forceinline__ void mma8(float* c, const unsigned* a, const unsigned* b) {
    asm volatile(
      "mma.sync.aligned.m16n8k8.row.col.f32.tf32.tf32.f32 "
      "{%0,%1,%2,%3}, {%4,%5,%6,%7}, {%8,%9}, {%0,%1,%2,%3};"
      : "+f"(c[0]), "+f"(c[1]), "+f"(c[2]), "+f"(c[3])
      : "r"(a[0]), "r"(a[1]), "r"(a[2]), "r"(a[3]), "r"(b[0]), "r"(b[1]));
}
__device__ __forceinline__ float silu_f(float s) {
    return s * __fdividef(1.0f, 1.0f + __expf(-s));
}

// ---------------------------------------------------------------------------
// Kernel 1: LayerNorm over D=512, warp-per-token (verified faster in R3)
// ---------------------------------------------------------------------------
__global__ void ln_x_kernel(const float* __restrict__ x) {
    int t = blockIdx.x * 8 + (threadIdx.x >> 5);
    int lane = threadIdx.x & 31;
    const float* row = x + (size_t)t * D_DIM + lane * 4;
    float4 v[4];
    #pragma unroll
    for (int w = 0; w < 4; w++) v[w] = *(const float4*)(row + w * 128);
    float s = 0.f, q = 0.f;
    #pragma unroll
    for (int w = 0; w < 4; w++) {
        s += v[w].x + v[w].y + v[w].z + v[w].w;
        q += v[w].x*v[w].x + v[w].y*v[w].y + v[w].z*v[w].z + v[w].w*v[w].w;
    }
    #pragma unroll
    for (int o = 16; o > 0; o >>= 1) {
        s += __shfl_xor_sync(0xffffffffu, s, o);
        q += __shfl_xor_sync(0xffffffffu, q, o);
    }
    float m = s * (1.0f / D_DIM);
    float r = rsqrtf(q * (1.0f / D_DIM) - m * m + EPS);
    float* dst = g_xn + (size_t)t * D_DIM + lane * 4;
    #pragma unroll
    for (int w = 0; w < 4; w++) {
        *(float4*)(dst + w * 128) = make_float4(
            (v[w].x - m) * r, (v[w].y - m) * r, (v[w].z - m) * r, (v[w].w - m) * r);
    }
}

// ---------------------------------------------------------------------------
// Kernel 2: h = silu(xn @ uvqk)  [6400,512]@[512,1024]  -- tf32 mma
// BM=128 BN=64 BK=16 (proven R2 config)
// ---------------------------------------------------------------------------
__global__ void gemm_uvqk_mma(const float* __restrict__ W) {
    __shared__ unsigned As[128 * 20];   // [m][k], stride 20
    __shared__ unsigned Bs[16 * 72];    // [k][n], stride 72
    int tid = threadIdx.x, lane = tid & 31, warp = tid >> 5;
    int wm = warp >> 1, wn = warp & 1;
    int m0 = blockIdx.y * 128, n0 = blockIdx.x * 64;

    float acc[2][4][4];
    #pragma unroll
    for (int a = 0; a < 2; a++)
        #pragma unroll
        for (int b = 0; b < 4; b++)
            #pragma unroll
            for (int c = 0; c < 4; c++) acc[a][b][c] = 0.f;

    int lr = tid >> 2, lk = (tid & 3) << 2;
    int bk = tid >> 4, bn = (tid & 15) << 2;
    const float* A0 = g_xn + (size_t)(m0 + lr) * D_DIM + lk;
    const float* A1 = A0 + (size_t)64 * D_DIM;

    for (int k0 = 0; k0 < D_DIM; k0 += 16) {
        float4 a0 = *(const float4*)(A0 + k0);
        float4 a1 = *(const float4*)(A1 + k0);
        float4 bv = *(const float4*)&W[(size_t)(k0 + bk) * HID + n0 + bn];
        __syncthreads();
        As[lr * 20 + lk + 0] = f2tf(a0.x);
        As[lr * 20 + lk + 1] = f2tf(a0.y);
        As[lr * 20 + lk + 2] = f2tf(a0.z);
        As[lr * 20 + lk + 3] = f2tf(a0.w);
        As[(lr + 64) * 20 + lk + 0] = f2tf(a1.x);
        As[(lr + 64) * 20 + lk + 1] = f2tf(a1.y);
        As[(lr + 64) * 20 + lk + 2] = f2tf(a1.z);
        As[(lr + 64) * 20 + lk + 3] = f2tf(a1.w);
        Bs[bk * 72 + bn + 0] = f2tf(bv.x);
        Bs[bk * 72 + bn + 1] = f2tf(bv.y);
        Bs[bk * 72 + bn + 2] = f2tf(bv.z);
        Bs[bk * 72 + bn + 3] = f2tf(bv.w);
        __syncthreads();
        #pragma unroll
        for (int ks = 0; ks < 2; ks++) {
            int kk = ks * 8 + (lane & 3);
            unsigned af[2][4];
            #pragma unroll
            for (int mm = 0; mm < 2; mm++) {
                int r = wm * 32 + mm * 16 + (lane >> 2);
                af[mm][0] = As[r * 20 + kk];
                af[mm][1] = As[(r + 8) * 20 + kk];
                af[mm][2] = As[r * 20 + kk + 4];
                af[mm][3] = As[(r + 8) * 20 + kk + 4];
            }
            #pragma unroll
            for (int nm = 0; nm < 4; nm++) {
                int cn = wn * 32 + nm * 8 + (lane >> 2);
                unsigned bf[2] = { Bs[kk * 72 + cn], Bs[(kk + 4) * 72 + cn] };
                mma8(acc[0][nm], af[0], bf);
                mma8(acc[1][nm], af[1], bf);
            }
        }
    }
    #pragma unroll
    for (int mm = 0; mm < 2; mm++) {
        #pragma unroll
        for (int nm = 0; nm < 4; nm++) {
            int r = m0 + wm * 32 + mm * 16 + (lane >> 2);
            int c = n0 + wn * 32 + nm * 8 + 2 * (lane & 3);
            *(float2*)&g_h[(size_t)r * HID + c] =
                make_float2(silu_f(acc[mm][nm][0]), silu_f(acc[mm][nm][1]));
            *(float2*)&g_h[(size_t)(r + 8) * HID + c] =
                make_float2(silu_f(acc[mm][nm][2]), silu_f(acc[mm][nm][3]));
        }
    }
}

// ---------------------------------------------------------------------------
// Kernel 3: jagged causal attention via tf32 mma (proven R2 64-row q-tiles)
// Per block: (q-tile, head). S^T = K @ Q^T ; P^T -> SMEM ; O += P @ V
// ---------------------------------------------------------------------------
#define A_QS 0
#define A_KS (64 * 72)
#define A_VS (A_KS + 64 * 68)
#define A_PS (A_VS + 64 * 72)
#define A_AUX (A_PS + 64 * 72)
#define ATTN_WORDS (A_AUX + 132 + 16 + 64 + 64)
#define SMEM_ATTN (ATTN_WORDS * 4)

__global__ void attn_mma(const int* __restrict__ ts, const float* __restrict__ tsw) {
    extern __shared__ unsigned sm[];
    unsigned* Qs = sm + A_QS;   // [d][i] stride 72 (transposed Q)
    unsigned* Ks = sm + A_KS;   // [j][d] stride 68
    unsigned* Vs = sm + A_VS;   // [j][l] stride 72
    unsigned* Ps = sm + A_PS;   // [j][i] stride 72 (P transposed)
    float* tw  = (float*)(sm + A_AUX);  // 129 (pad 132)
    float* thf = tw + 132;              // 16
    int* tqs = (int*)(thf + 16);        // 64
    int* tks = tqs + 64;                // 64

    int b  = c_ord[blockIdx.x][0];      // exact qt-descending schedule
    int qt = c_ord[blockIdx.x][1];
    int head = blockIdx.y;
    int tok0 = c_off[b] + qt * 64;

    int tid = threadIdx.x, lane = tid & 31, warp = tid >> 5;
    int wm = warp >> 1, wn = warp & 1;

    // stage Q transposed (once per block)
    const float* qb = g_h + 512 + head * 64;
    for (int i = tid; i < 1024; i += 256) {
        int r = i >> 4, c = (i & 15) << 2;
        float4 v = *(const float4*)&qb[(size_t)(tok0 + r) * HID + c];
        Qs[(c + 0) * 72 + r] = f2tf(v.x);
        Qs[(c + 1) * 72 + r] = f2tf(v.y);
        Qs[(c + 2) * 72 + r] = f2tf(v.z);
        Qs[(c + 3) * 72 + r] = f2tf(v.w);
    }
    for (int i = tid; i < 129; i += 256) tw[i] = tsw[i];
    if (tid < 64) tqs[tid] = ts[b * N_SEQ + qt * 64 + tid];
    if (tid < 15) {
        if (tid == 0) thf[0] = 0.f;
        else {
            int k = tid;
            int t = (int)(expf((float)k)) - 9;
            if (t < 1) t = 1;
            while (t > 1 && log1pf((float)(t - 1)) >= (float)k) --t;
            while (log1pf((float)t) < (float)k) ++t;
            thf[k] = (float)t;
        }
    }
    __syncthreads();
    float th[14];
    #pragma unroll
    for (int k = 0; k < 14; k++) th[k] = thf[k + 1];

    float accO[4][4];
    #pragma unroll
    for (int a = 0; a < 4; a++)
        #pragma unroll
        for (int c = 0; c < 4; c++) accO[a][c] = 0.f;

    const float* kb = g_h + 768 + head * 64;
    const float* vb = g_h + 256 + head * 64;

    for (int jt = 0; jt <= qt; ++jt) {
        __syncthreads();
        int ktok = c_off[b] + jt * 64;
        for (int i = tid; i < 1024; i += 256) {
            int r = i >> 4, c = (i & 15) << 2;
            float4 kv = *(const float4*)&kb[(size_t)(ktok + r) * HID + c];
            float4 vv = *(const float4*)&vb[(size_t)(ktok + r) * HID + c];
            *(uint4*)&Ks[r * 68 + c] =
                make_uint4(f2tf(kv.x), f2tf(kv.y), f2tf(kv.z), f2tf(kv.w));
            *(uint4*)&Vs[r * 72 + c] =
                make_uint4(f2tf(vv.x), f2tf(vv.y), f2tf(vv.z), f2tf(vv.w));
        }
        if (tid < 64) tks[tid] = ts[b * N_SEQ + jt * 64 + tid];
        __syncthreads();

        // S^T[j][i] = sum_d K[j][d] Q[i][d]
        float accS[4][4];
        #pragma unroll
        for (int a = 0; a < 4; a++)
            #pragma unroll
            for (int c = 0; c < 4; c++) accS[a][c] = 0.f;
        #pragma unroll
        for (int ks = 0; ks < 8; ks++) {
            int kk = ks * 8 + (lane & 3);
            int jr = wm * 16 + (lane >> 2);
            unsigned af[4];
            af[0] = Ks[jr * 68 + kk];
            af[1] = Ks[(jr + 8) * 68 + kk];
            af[2] = Ks[jr * 68 + kk + 4];
            af[3] = Ks[(jr + 8) * 68 + kk + 4];
            #pragma unroll
            for (int nm = 0; nm < 4; nm++) {
                int ic = wn * 32 + nm * 8 + (lane >> 2);
                unsigned bf[2] = { Qs[kk * 72 + ic], Qs[(kk + 4) * 72 + ic] };
                mma8(accS[nm], af, bf);
            }
        }

        // bias + silu + causal -> Ps (transposed)
        bool full = (jt < qt);
        #pragma unroll
        for (int nm = 0; nm < 4; nm++) {
            #pragma unroll
            for (int e = 0; e < 4; e++) {
                int j = wm * 16 + (lane >> 2) + ((e & 2) ? 8 : 0);
                int i = wn * 32 + nm * 8 + 2 * (lane & 3) + (e & 1);
                float p = 0.f;
                if (full || j <= i) {
                    float fd = fabsf((float)(tqs[i] - tks[j]));
                    int bkt = 0;
                    #pragma unroll
                    for (int k = 0; k < 14; k++) bkt += (fd >= th[k]) ? 1 : 0;
                    float s = accS[nm][e] + tw[bkt];
                    p = silu_f(s) * INV_N;
                }
                Ps[j * 72 + i] = f2tf(p);
            }
        }
        __syncthreads();

        // O[i][l] += sum_j P[i][j] V[j][l]
        #pragma unroll
        for (int ks = 0; ks < 8; ks++) {
            int kk = ks * 8 + (lane & 3);
            int ir = wm * 16 + (lane >> 2);
            unsigned af[4];
            af[0] = Ps[kk * 72 + ir];
            af[1] = Ps[kk * 72 + ir + 8];
            af[2] = Ps[(kk + 4) * 72 + ir];
            af[3] = Ps[(kk + 4) * 72 + ir + 8];
            #pragma unroll
            for (int nm = 0; nm < 4; nm++) {
                int lc = wn * 32 + nm * 8 + (lane >> 2);
                unsigned bf[2] = { Vs[kk * 72 + lc], Vs[(kk + 4) * 72 + lc] };
                mma8(accO[nm], af, bf);
            }
        }
    }

    #pragma unroll
    for (int nm = 0; nm < 4; nm++) {
        int i = wm * 16 + (lane >> 2);
        int l = wn * 32 + nm * 8 + 2 * (lane & 3);
        *(float2*)&g_attn[(size_t)(tok0 + i) * 256 + head * 64 + l] =
            make_float2(accO[nm][0], accO[nm][1]);
        *(float2*)&g_attn[(size_t)(tok0 + i + 8) * 256 + head * 64 + l] =
            make_float2(accO[nm][2], accO[nm][3]);
    }
}

// ---------------------------------------------------------------------------
// Kernel 4: oin = u * LN(attn), warp-per-token (verified faster in R3)
// ---------------------------------------------------------------------------
__global__ void oin_kernel() {
    int t = blockIdx.x * 8 + (threadIdx.x >> 5);
    int lane = threadIdx.x & 31;
    const float* row = g_attn + (size_t)t * 256 + lane * 4;
    float4 a0 = *(const float4*)(row);
    float4 a1 = *(const float4*)(row + 128);
    float s = a0.x + a0.y + a0.z + a0.w + a1.x + a1.y + a1.z + a1.w;
    float q = a0.x*a0.x + a0.y*a0.y + a0.z*a0.z + a0.w*a0.w
            + a1.x*a1.x + a1.y*a1.y + a1.z*a1.z + a1.w*a1.w;
    #pragma unroll
    for (int o = 16; o > 0; o >>= 1) {
        s += __shfl_xor_sync(0xffffffffu, s, o);
        q += __shfl_xor_sync(0xffffffffu, q, o);
    }
    float m = s * (1.0f / 256.0f);
    float r = rsqrtf(q * (1.0f / 256.0f) - m * m + EPS);
    const float* up = g_h + (size_t)t * HID + lane * 4;
    float4 u0 = *(const float4*)(up);
    float4 u1 = *(const float4*)(up + 128);
    float* dst = g_oin + (size_t)t * 256 + lane * 4;
    *(float4*)(dst) = make_float4(u0.x * (a0.x - m) * r, u0.y * (a0.y - m) * r,
                                  u0.z * (a0.z - m) * r, u0.w * (a0.w - m) * r);
    *(float4*)(dst + 128) = make_float4(u1.x * (a1.x - m) * r, u1.y * (a1.y - m) * r,
                                        u1.z * (a1.z - m) * r, u1.w * (a1.w - m) * r);
}

// ---------------------------------------------------------------------------
// Kernel 5: out = oin @ o_w^T + o_b + x  [6400,256]@[256,512] -- tf32 mma, BK=16
// ---------------------------------------------------------------------------
__global__ void gemm_out_mma(const float* __restrict__ Wo,    // [512,256]
                             const float* __restrict__ bias,  // [512]
                             const float* __restrict__ x,
                             float* __restrict__ out) {
    __shared__ unsigned As[128 * 20];
    __shared__ unsigned Bs[16 * 72];
    int tid = threadIdx.x, lane = tid & 31, warp = tid >> 5;
    int wm = warp >> 1, wn = warp & 1;
    int m0 = blockIdx.y * 128, n0 = blockIdx.x * 64;

    float acc[2][4][4];
    #pragma unroll
    for (int a = 0; a < 2; a++)
        #pragma unroll
        for (int b = 0; b < 4; b++)
            #pragma unroll
            for (int c = 0; c < 4; c++) acc[a][b][c] = 0.f;

    int lr = tid >> 2, lk = (tid & 3) << 2;
    int bn = tid & 63, bk4 = (tid >> 6) << 2;

    for (int k0 = 0; k0 < 256; k0 += 16) {
        float4 a0 = *(const float4*)&g_oin[(size_t)(m0 + lr) * 256 + k0 + lk];
        float4 a1 = *(const float4*)&g_oin[(size_t)(m0 + lr + 64) * 256 + k0 + lk];
        float4 wv = *(const float4*)&Wo[(size_t)(n0 + bn) * 256 + k0 + bk4];
        __syncthreads();
        As[lr * 20 + lk + 0] = f2tf(a0.x);
        As[lr * 20 + lk + 1] = f2tf(a0.y);
        As[lr * 20 + lk + 2] = f2tf(a0.z);
        As[lr * 20 + lk + 3] = f2tf(a0.w);
        As[(lr + 64) * 20 + lk + 0] = f2tf(a1.x);
        As[(lr + 64) * 20 + lk + 1] = f2tf(a1.y);
        As[(lr + 64) * 20 + lk + 2] = f2tf(a1.z);
        As[(lr + 64) * 20 + lk + 3] = f2tf(a1.w);
        Bs[(bk4 + 0) * 72 + bn] = f2tf(wv.x);   // transpose o_w -> [k][n]
        Bs[(bk4 + 1) * 72 + bn] = f2tf(wv.y);
        Bs[(bk4 + 2) * 72 + bn] = f2tf(wv.z);
        Bs[(bk4 + 3) * 72 + bn] = f2tf(wv.w);
        __syncthreads();
        #pragma unroll
        for (int ks = 0; ks < 2; ks++) {
            int kk = ks * 8 + (lane & 3);
            unsigned af[2][4];
            #pragma unroll
            for (int mm = 0; mm < 2; mm++) {
                int r = wm * 32 + mm * 16 + (lane >> 2);
                af[mm][0] = As[r * 20 + kk];
                af[mm][1] = As[(r + 8) * 20 + kk];
                af[mm][2] = As[r * 20 + kk + 4];
                af[mm][3] = As[(r + 8) * 20 + kk + 4];
            }
            #pragma unroll
            for (int nm = 0; nm < 4; nm++) {
                int cn = wn * 32 + nm * 8 + (lane >> 2);
                unsigned bf[2] = { Bs[kk * 72 + cn], Bs[(kk + 4) * 72 + cn] };
                mma8(acc[0][nm], af[0], bf);
                mma8(acc[1][nm], af[1], bf);
            }
        }
    }
    #pragma unroll
    for (int mm = 0; mm < 2; mm++) {
        #pragma unroll
        for (int nm = 0; nm < 4; nm++) {
            int r = m0 + wm * 32 + mm * 16 + (lane >> 2);
            int c = n0 + wn * 32 + nm * 8 + 2 * (lane & 3);
            float2 xr0 = *(const float2*)&x[(size_t)r * D_DIM + c];
            float2 xr1 = *(const float2*)&x[(size_t)(r + 8) * D_DIM + c];
            float b0 = bias[c], b1 = bias[c + 1];
            *(float2*)&out[(size_t)r * D_DIM + c] =
                make_float2(acc[mm][nm][0] + b0 + xr0.x, acc[mm][nm][1] + b1 + xr0.y);
            *(float2*)&out[(size_t)(r + 8) * D_DIM + c] =
                make_float2(acc[mm][nm][2] + b0 + xr1.x, acc[mm][nm][3] + b1 + xr1.y);
        }
    }
}

// ---------------------------------------------------------------------------
// Launcher
// ---------------------------------------------------------------------------
extern "C" void kernel_launch(void* const* d_in, const int* in_sizes, int n_in,
                              void* d_out, int out_size) {
    const float* x    = (const float*)d_in[0];
    const float* uvqk = (const float*)d_in[1];
    const float* o_w  = (const float*)d_in[2];
    const float* o_b  = (const float*)d_in[3];
    const float* ts_w = (const float*)d_in[4];
    const int*   ts   = (const int*)d_in[5];
    float* out = (float*)d_out;

    ln_x_kernel<<<T_TOK / 8, 256>>>(x);
    gemm_uvqk_mma<<<dim3(HID / 64, T_TOK / 128), 256>>>(uvqk);

    cudaFuncSetAttribute(attn_mma,
                         cudaFuncAttributeMaxDynamicSharedMemorySize, SMEM_ATTN);
    attn_mma<<<dim3(100, 4), 256, SMEM_ATTN>>>(ts, ts_w);

    oin_kernel<<<T_TOK / 8, 256>>>();
    gemm_out_mma<<<dim3(D_DIM / 64, T_TOK / 128), 256>>>(o_w, o_b, x, out);
}

// round 8
// speedup vs baseline: 1.5479x; 1.1842x over previous
#include <cuda_runtime.h>
#include <cuda_bf16.h>
#include <cuda_fp16.h>
#include <math.h>

// ---------------------------------------------------------------------------
// Problem constants
// ---------------------------------------------------------------------------
#define T_TOK   6400
#define D_DIM   512
#define HID     1024
#define N_SEQ   2048
#define EPS     1e-6f
#define INV_N   (1.0f/2048.0f)

__device__ __constant__ int c_off[5] = {0, 2048, 3584, 4608, 6400};
// (batch, qt) for 64-row q-tiles, exact qt-descending order (longest first).
__device__ __constant__ unsigned char c_ord[100][2] = {
 {0,31},{0,30},{0,29},{0,28},
 {0,27},{3,27},{0,26},{3,26},{0,25},{3,25},{0,24},{3,24},
 {0,23},{1,23},{3,23},{0,22},{1,22},{3,22},{0,21},{1,21},{3,21},
 {0,20},{1,20},{3,20},{0,19},{1,19},{3,19},{0,18},{1,18},{3,18},
 {0,17},{1,17},{3,17},{0,16},{1,16},{3,16},
 {0,15},{1,15},{2,15},{3,15},{0,14},{1,14},{2,14},{3,14},
 {0,13},{1,13},{2,13},{3,13},{0,12},{1,12},{2,12},{3,12},
 {0,11},{1,11},{2,11},{3,11},{0,10},{1,10},{2,10},{3,10},
 {0,9},{1,9},{2,9},{3,9},{0,8},{1,8},{2,8},{3,8},
 {0,7},{1,7},{2,7},{3,7},{0,6},{1,6},{2,6},{3,6},
 {0,5},{1,5},{2,5},{3,5},{0,4},{1,4},{2,4},{3,4},
 {0,3},{1,3},{2,3},{3,3},{0,2},{1,2},{2,2},{3,2},
 {0,1},{1,1},{2,1},{3,1},{0,0},{1,0},{2,0},{3,0}};

// ---------------------------------------------------------------------------
// Scratch
// ---------------------------------------------------------------------------
__device__ float g_xn  [T_TOK * D_DIM];
__device__ float g_h   [T_TOK * HID];     // u|v|q|k
__device__ float g_attn[T_TOK * 256];
__device__ float g_oin [T_TOK * 256];

// ---------------------------------------------------------------------------
// helpers
// ---------------------------------------------------------------------------
__device__ __forceinline__ unsigned f2tf(float x) {
    unsigned u; asm("cvt.rna.tf32.f32 %0, %1;" : "=r"(u) : "f"(x)); return u;
}
__device__ __forceinline__ void mma8(float* c, const unsigned* a, const unsigned* b) {
    asm volatile(
      "mma.sync.aligned.m16n8k8.row.col.f32.tf32.tf32.f32 "
      "{%0,%1,%2,%3}, {%4,%5,%6,%7}, {%8,%9}, {%0,%1,%2,%3};"
      : "+f"(c[0]), "+f"(c[1]), "+f"(c[2]), "+f"(c[3])
      : "r"(a[0]), "r"(a[1]), "r"(a[2]), "r"(a[3]), "r"(b[0]), "r"(b[1]));
}
__device__ __forceinline__ void mma16(float* c, const unsigned* a, unsigned b0, unsigned b1) {
    asm volatile(
      "mma.sync.aligned.m16n8k16.row.col.f32.f16.f16.f32 "
      "{%0,%1,%2,%3}, {%4,%5,%6,%7}, {%8,%9}, {%0,%1,%2,%3};"
      : "+f"(c[0]), "+f"(c[1]), "+f"(c[2]), "+f"(c[3])
      : "r"(a[0]), "r"(a[1]), "r"(a[2]), "r"(a[3]), "r"(b0), "r"(b1));
}
__device__ __forceinline__ void ldsm4(unsigned* r, unsigned addr) {
    asm volatile("ldmatrix.sync.aligned.m8n8.x4.shared.b16 {%0,%1,%2,%3}, [%4];"
        : "=r"(r[0]), "=r"(r[1]), "=r"(r[2]), "=r"(r[3]) : "r"(addr));
}
__device__ __forceinline__ void ldsm4t(unsigned* r, unsigned addr) {
    asm volatile("ldmatrix.sync.aligned.m8n8.x4.trans.shared.b16 {%0,%1,%2,%3}, [%4];"
        : "=r"(r[0]), "=r"(r[1]), "=r"(r[2]), "=r"(r[3]) : "r"(addr));
}
__device__ __forceinline__ unsigned packh2(float x, float y) {
    __half2 h = __floats2half2_rn(x, y);
    return *(unsigned*)&h;
}
__device__ __forceinline__ float silu_f(float s) {
    return s * __fdividef(1.0f, 1.0f + __expf(-s));
}

// ---------------------------------------------------------------------------
// Kernel 1: LayerNorm over D=512, warp-per-token
// ---------------------------------------------------------------------------
__global__ void ln_x_kernel(const float* __restrict__ x) {
    int t = blockIdx.x * 8 + (threadIdx.x >> 5);
    int lane = threadIdx.x & 31;
    const float* row = x + (size_t)t * D_DIM + lane * 4;
    float4 v[4];
    #pragma unroll
    for (int w = 0; w < 4; w++) v[w] = *(const float4*)(row + w * 128);
    float s = 0.f, q = 0.f;
    #pragma unroll
    for (int w = 0; w < 4; w++) {
        s += v[w].x + v[w].y + v[w].z + v[w].w;
        q += v[w].x*v[w].x + v[w].y*v[w].y + v[w].z*v[w].z + v[w].w*v[w].w;
    }
    #pragma unroll
    for (int o = 16; o > 0; o >>= 1) {
        s += __shfl_xor_sync(0xffffffffu, s, o);
        q += __shfl_xor_sync(0xffffffffu, q, o);
    }
    float m = s * (1.0f / D_DIM);
    float r = rsqrtf(q * (1.0f / D_DIM) - m * m + EPS);
    float* dst = g_xn + (size_t)t * D_DIM + lane * 4;
    #pragma unroll
    for (int w = 0; w < 4; w++) {
        *(float4*)(dst + w * 128) = make_float4(
            (v[w].x - m) * r, (v[w].y - m) * r, (v[w].z - m) * r, (v[w].w - m) * r);
    }
}

// ---------------------------------------------------------------------------
// Kernel 2: h = silu(xn @ uvqk)  [6400,512]@[512,1024]  -- tf32 mma (proven)
// ---------------------------------------------------------------------------
__global__ void gemm_uvqk_mma(const float* __restrict__ W) {
    __shared__ unsigned As[128 * 20];
    __shared__ unsigned Bs[16 * 72];
    int tid = threadIdx.x, lane = tid & 31, warp = tid >> 5;
    int wm = warp >> 1, wn = warp & 1;
    int m0 = blockIdx.y * 128, n0 = blockIdx.x * 64;

    float acc[2][4][4];
    #pragma unroll
    for (int a = 0; a < 2; a++)
        #pragma unroll
        for (int b = 0; b < 4; b++)
            #pragma unroll
            for (int c = 0; c < 4; c++) acc[a][b][c] = 0.f;

    int lr = tid >> 2, lk = (tid & 3) << 2;
    int bk = tid >> 4, bn = (tid & 15) << 2;
    const float* A0 = g_xn + (size_t)(m0 + lr) * D_DIM + lk;
    const float* A1 = A0 + (size_t)64 * D_DIM;

    for (int k0 = 0; k0 < D_DIM; k0 += 16) {
        float4 a0 = *(const float4*)(A0 + k0);
        float4 a1 = *(const float4*)(A1 + k0);
        float4 bv = *(const float4*)&W[(size_t)(k0 + bk) * HID + n0 + bn];
        __syncthreads();
        As[lr * 20 + lk + 0] = f2tf(a0.x);
        As[lr * 20 + lk + 1] = f2tf(a0.y);
        As[lr * 20 + lk + 2] = f2tf(a0.z);
        As[lr * 20 + lk + 3] = f2tf(a0.w);
        As[(lr + 64) * 20 + lk + 0] = f2tf(a1.x);
        As[(lr + 64) * 20 + lk + 1] = f2tf(a1.y);
        As[(lr + 64) * 20 + lk + 2] = f2tf(a1.z);
        As[(lr + 64) * 20 + lk + 3] = f2tf(a1.w);
        Bs[bk * 72 + bn + 0] = f2tf(bv.x);
        Bs[bk * 72 + bn + 1] = f2tf(bv.y);
        Bs[bk * 72 + bn + 2] = f2tf(bv.z);
        Bs[bk * 72 + bn + 3] = f2tf(bv.w);
        __syncthreads();
        #pragma unroll
        for (int ks = 0; ks < 2; ks++) {
            int kk = ks * 8 + (lane & 3);
            unsigned af[2][4];
            #pragma unroll
            for (int mm = 0; mm < 2; mm++) {
                int r = wm * 32 + mm * 16 + (lane >> 2);
                af[mm][0] = As[r * 20 + kk];
                af[mm][1] = As[(r + 8) * 20 + kk];
                af[mm][2] = As[r * 20 + kk + 4];
                af[mm][3] = As[(r + 8) * 20 + kk + 4];
            }
            #pragma unroll
            for (int nm = 0; nm < 4; nm++) {
                int cn = wn * 32 + nm * 8 + (lane >> 2);
                unsigned bf[2] = { Bs[kk * 72 + cn], Bs[(kk + 4) * 72 + cn] };
                mma8(acc[0][nm], af[0], bf);
                mma8(acc[1][nm], af[1], bf);
            }
        }
    }
    #pragma unroll
    for (int mm = 0; mm < 2; mm++) {
        #pragma unroll
        for (int nm = 0; nm < 4; nm++) {
            int r = m0 + wm * 32 + mm * 16 + (lane >> 2);
            int c = n0 + wn * 32 + nm * 8 + 2 * (lane & 3);
            *(float2*)&g_h[(size_t)r * HID + c] =
                make_float2(silu_f(acc[mm][nm][0]), silu_f(acc[mm][nm][1]));
            *(float2*)&g_h[(size_t)(r + 8) * HID + c] =
                make_float2(silu_f(acc[mm][nm][2]), silu_f(acc[mm][nm][3]));
        }
    }
}

// ---------------------------------------------------------------------------
// Kernel 3: jagged causal attention, fp16 mma + ldmatrix
// S[i][j] = Q K^T (fp16, f32 accum); P kept in registers (C->A frag reuse);
// O[i][l] += P V. Per-warp j-slice partial O, cross-warp add at end.
// ---------------------------------------------------------------------------
#define HS 72                         // half stride per row (144 B)
#define SM_Q  0                       // 64*72 halves = 9216 B
#define SM_K  9216
#define SM_V  18432
#define SM_TW 27648                   // 132 floats
#define SM_TH 28176                   // 16 floats
#define SM_TQ 28240                   // 64 ints
#define SM_TK 28496                   // 64 ints
#define SM_TOT 28752                  // red (16 KB) aliases SM_Q..SM_K

__global__ void __launch_bounds__(256, 2)
attn_mma(const int* __restrict__ ts, const float* __restrict__ tsw) {
    __shared__ __align__(16) unsigned char smb[SM_TOT];
    __half* Qh = (__half*)(smb + SM_Q);
    __half* Kh = (__half*)(smb + SM_K);
    __half* Vh = (__half*)(smb + SM_V);
    float*  red = (float*)smb;                 // [32][4][32] floats, reuse Q/K
    float*  tw  = (float*)(smb + SM_TW);
    float*  thf = (float*)(smb + SM_TH);
    int*    tqs = (int*)(smb + SM_TQ);
    int*    tks = (int*)(smb + SM_TK);

    int b  = c_ord[blockIdx.x][0];
    int qt = c_ord[blockIdx.x][1];
    int head = blockIdx.y;
    int tok0 = c_off[b] + qt * 64;

    int tid = threadIdx.x, lane = tid & 31, warp = tid >> 5;
    int wm = warp >> 1, wn = warp & 1;       // i-tile (16 rows), j-half (32 cols)
    int i0 = wm * 16;
    int gid = lane >> 2, tig = lane & 3;     // fragment row group / pair col

    unsigned qbase = (unsigned)__cvta_generic_to_shared(Qh);
    unsigned kbase = (unsigned)__cvta_generic_to_shared(Kh);
    unsigned vbase = (unsigned)__cvta_generic_to_shared(Vh);

    // stage Q (row-major halves), tw, thresholds, q timestamps
    const float* qb = g_h + 512 + head * 64;
    for (int i = tid; i < 1024; i += 256) {
        int r = i >> 4, c = (i & 15) << 2;
        float4 v = *(const float4*)&qb[(size_t)(tok0 + r) * HID + c];
        *(uint2*)(Qh + r * HS + c) =
            make_uint2(packh2(v.x, v.y), packh2(v.z, v.w));
    }
    for (int i = tid; i < 129; i += 256) tw[i] = tsw[i];
    if (tid < 64) tqs[tid] = ts[b * N_SEQ + qt * 64 + tid];
    if (tid < 15) {
        if (tid == 0) thf[0] = 0.f;
        else {
            int k = tid;
            int t = (int)(expf((float)k)) - 9;
            if (t < 1) t = 1;
            while (t > 1 && log1pf((float)(t - 1)) >= (float)k) --t;
            while (log1pf((float)t) < (float)k) ++t;
            thf[k] = (float)t;
        }
    }
    __syncthreads();
    float th[14];
    #pragma unroll
    for (int k = 0; k < 14; k++) th[k] = thf[k + 1];
    int tq0 = tqs[i0 + gid];
    int tq8 = tqs[i0 + gid + 8];

    float accO[8][4];
    #pragma unroll
    for (int t = 0; t < 8; t++)
        #pragma unroll
        for (int c = 0; c < 4; c++) accO[t][c] = 0.f;

    const float* kb = g_h + 768 + head * 64;
    const float* vb = g_h + 256 + head * 64;

    // ldmatrix lane-address components (elements; *2 for bytes)
    int a_row = lane & 15, a_col = (lane >> 4) * 8;            // A (Q,P-style)
    int b_row = ((lane >> 4) * 8) + (lane & 7);                 // B no-trans (K)
    int b_col = ((lane >> 3) & 1) * 8;
    int v_row = (lane & 7) + ((lane >> 3) & 1) * 8;             // B trans (V)
    int v_col = (lane >> 4) * 8;

    for (int jt = 0; jt <= qt; ++jt) {
        int ktok = c_off[b] + jt * 64;
        __syncthreads();    // prior iteration done reading Kh/Vh
        for (int i = tid; i < 1024; i += 256) {
            int r = i >> 4, c = (i & 15) << 2;
            float4 kv = *(const float4*)&kb[(size_t)(ktok + r) * HID + c];
            float4 vv = *(const float4*)&vb[(size_t)(ktok + r) * HID + c];
            *(uint2*)(Kh + r * HS + c) =
                make_uint2(packh2(kv.x, kv.y), packh2(kv.z, kv.w));
            *(uint2*)(Vh + r * HS + c) =
                make_uint2(packh2(vv.x, vv.y), packh2(vv.z, vv.w));
        }
        if (tid < 64) tks[tid] = ts[b * N_SEQ + jt * 64 + tid];
        __syncthreads();

        // ---- S[i][j] = Q K^T  (warp: 16i x 32j, k=64)
        float accS[4][4];
        #pragma unroll
        for (int a = 0; a < 4; a++)
            #pragma unroll
            for (int c = 0; c < 4; c++) accS[a][c] = 0.f;
        #pragma unroll
        for (int kc = 0; kc < 4; kc++) {
            int d0 = kc * 16;
            unsigned af[4];
            ldsm4(af, qbase + ((i0 + a_row) * HS + d0 + a_col) * 2);
            #pragma unroll
            for (int hh = 0; hh < 2; hh++) {
                int j0 = wn * 32 + hh * 16;
                unsigned bf[4];
                ldsm4(bf, kbase + ((j0 + b_row) * HS + d0 + b_col) * 2);
                mma16(accS[hh * 2],     af, bf[0], bf[1]);
                mma16(accS[hh * 2 + 1], af, bf[2], bf[3]);
            }
        }

        // ---- epilogue: bias + silu + causal (INV_N deferred to O writeout)
        bool full = (jt < qt);
        #pragma unroll
        for (int nm = 0; nm < 4; nm++) {
            #pragma unroll
            for (int e = 0; e < 4; e++) {
                int i = i0 + gid + ((e & 2) ? 8 : 0);
                int j = wn * 32 + nm * 8 + tig * 2 + (e & 1);
                float p = 0.f;
                if (full || j <= i) {
                    int tq = (e & 2) ? tq8 : tq0;
                    float fd = fabsf((float)(tq - tks[j]));
                    int bkt = 0;
                    #pragma unroll
                    for (int k = 0; k < 14; k++) bkt += (fd >= th[k]) ? 1 : 0;
                    p = silu_f(accS[nm][e] + tw[bkt]);
                }
                accS[nm][e] = p;
            }
        }

        // ---- convert C-frags -> A-frags in registers (no smem round trip)
        unsigned pa[2][4];
        #pragma unroll
        for (int kc = 0; kc < 2; kc++) {
            pa[kc][0] = packh2(accS[2*kc][0],     accS[2*kc][1]);
            pa[kc][1] = packh2(accS[2*kc][2],     accS[2*kc][3]);
            pa[kc][2] = packh2(accS[2*kc+1][0],   accS[2*kc+1][1]);
            pa[kc][3] = packh2(accS[2*kc+1][2],   accS[2*kc+1][3]);
        }

        // ---- O[i][l] += P V over this warp's j-slice (k = wn*32 .. +32)
        #pragma unroll
        for (int kc = 0; kc < 2; kc++) {
            int jc = wn * 32 + kc * 16;
            #pragma unroll
            for (int lt = 0; lt < 4; lt++) {
                int l0 = lt * 16;
                unsigned bf[4];
                ldsm4t(bf, vbase + ((jc + v_row) * HS + l0 + v_col) * 2);
                mma16(accO[lt * 2],     pa[kc], bf[0], bf[1]);
                mma16(accO[lt * 2 + 1], pa[kc], bf[2], bf[3]);
            }
        }
    }

    // ---- cross-warp reduction of the two j-halves, then writeout
    __syncthreads();               // Q/K smem dead; safe to alias as red
    if (wn == 1) {
        #pragma unroll
        for (int t = 0; t < 8; t++)
            #pragma unroll
            for (int e = 0; e < 4; e++)
                red[((t * 4 + e) * 4 + wm) * 32 + lane] = accO[t][e];
    }
    __syncthreads();
    if (wn == 0) {
        #pragma unroll
        for (int t = 0; t < 8; t++)
            #pragma unroll
            for (int e = 0; e < 4; e++)
                accO[t][e] += red[((t * 4 + e) * 4 + wm) * 32 + lane];
        #pragma unroll
        for (int nt = 0; nt < 8; nt++) {
            int i = tok0 + i0 + gid;
            int l = head * 64 + nt * 8 + tig * 2;
            *(float2*)&g_attn[(size_t)i * 256 + l] =
                make_float2(accO[nt][0] * INV_N, accO[nt][1] * INV_N);
            *(float2*)&g_attn[(size_t)(i + 8) * 256 + l] =
                make_float2(accO[nt][2] * INV_N, accO[nt][3] * INV_N);
        }
    }
}

// ---------------------------------------------------------------------------
// Kernel 4: oin = u * LN(attn), warp-per-token
// ---------------------------------------------------------------------------
__global__ void oin_kernel() {
    int t = blockIdx.x * 8 + (threadIdx.x >> 5);
    int lane = threadIdx.x & 31;
    const float* row = g_attn + (size_t)t * 256 + lane * 4;
    float4 a0 = *(const float4*)(row);
    float4 a1 = *(const float4*)(row + 128);
    float s = a0.x + a0.y + a0.z + a0.w + a1.x + a1.y + a1.z + a1.w;
    float q = a0.x*a0.x + a0.y*a0.y + a0.z*a0.z + a0.w*a0.w
            + a1.x*a1.x + a1.y*a1.y + a1.z*a1.z + a1.w*a1.w;
    #pragma unroll
    for (int o = 16; o > 0; o >>= 1) {
        s += __shfl_xor_sync(0xffffffffu, s, o);
        q += __shfl_xor_sync(0xffffffffu, q, o);
    }
    float m = s * (1.0f / 256.0f);
    float r = rsqrtf(q * (1.0f / 256.0f) - m * m + EPS);
    const float* up = g_h + (size_t)t * HID + lane * 4;
    float4 u0 = *(const float4*)(up);
    float4 u1 = *(const float4*)(up + 128);
    float* dst = g_oin + (size_t)t * 256 + lane * 4;
    *(float4*)(dst) = make_float4(u0.x * (a0.x - m) * r, u0.y * (a0.y - m) * r,
                                  u0.z * (a0.z - m) * r, u0.w * (a0.w - m) * r);
    *(float4*)(dst + 128) = make_float4(u1.x * (a1.x - m) * r, u1.y * (a1.y - m) * r,
                                        u1.z * (a1.z - m) * r, u1.w * (a1.w - m) * r);
}

// ---------------------------------------------------------------------------
// Kernel 5: out = oin @ o_w^T + o_b + x  [6400,256]@[256,512] -- tf32 mma
// ---------------------------------------------------------------------------
__global__ void gemm_out_mma(const float* __restrict__ Wo,
                             const float* __restrict__ bias,
                             const float* __restrict__ x,
                             float* __restrict__ out) {
    __shared__ unsigned As[128 * 20];
    __shared__ unsigned Bs[16 * 72];
    int tid = threadIdx.x, lane = tid & 31, warp = tid >> 5;
    int wm = warp >> 1, wn = warp & 1;
    int m0 = blockIdx.y * 128, n0 = blockIdx.x * 64;

    float acc[2][4][4];
    #pragma unroll
    for (int a = 0; a < 2; a++)
        #pragma unroll
        for (int b = 0; b < 4; b++)
            #pragma unroll
            for (int c = 0; c < 4; c++) acc[a][b][c] = 0.f;

    int lr = tid >> 2, lk = (tid & 3) << 2;
    int bn = tid & 63, bk4 = (tid >> 6) << 2;

    for (int k0 = 0; k0 < 256; k0 += 16) {
        float4 a0 = *(const float4*)&g_oin[(size_t)(m0 + lr) * 256 + k0 + lk];
        float4 a1 = *(const float4*)&g_oin[(size_t)(m0 + lr + 64) * 256 + k0 + lk];
        float4 wv = *(const float4*)&Wo[(size_t)(n0 + bn) * 256 + k0 + bk4];
        __syncthreads();
        As[lr * 20 + lk + 0] = f2tf(a0.x);
        As[lr * 20 + lk + 1] = f2tf(a0.y);
        As[lr * 20 + lk + 2] = f2tf(a0.z);
        As[lr * 20 + lk + 3] = f2tf(a0.w);
        As[(lr + 64) * 20 + lk + 0] = f2tf(a1.x);
        As[(lr + 64) * 20 + lk + 1] = f2tf(a1.y);
        As[(lr + 64) * 20 + lk + 2] = f2tf(a1.z);
        As[(lr + 64) * 20 + lk + 3] = f2tf(a1.w);
        Bs[(bk4 + 0) * 72 + bn] = f2tf(wv.x);
        Bs[(bk4 + 1) * 72 + bn] = f2tf(wv.y);
        Bs[(bk4 + 2) * 72 + bn] = f2tf(wv.z);
        Bs[(bk4 + 3) * 72 + bn] = f2tf(wv.w);
        __syncthreads();
        #pragma unroll
        for (int ks = 0; ks < 2; ks++) {
            int kk = ks * 8 + (lane & 3);
            unsigned af[2][4];
            #pragma unroll
            for (int mm = 0; mm < 2; mm++) {
                int r = wm * 32 + mm * 16 + (lane >> 2);
                af[mm][0] = As[r * 20 + kk];
                af[mm][1] = As[(r + 8) * 20 + kk];
                af[mm][2] = As[r * 20 + kk + 4];
                af[mm][3] = As[(r + 8) * 20 + kk + 4];
            }
            #pragma unroll
            for (int nm = 0; nm < 4; nm++) {
                int cn = wn * 32 + nm * 8 + (lane >> 2);
                unsigned bf[2] = { Bs[kk * 72 + cn], Bs[(kk + 4) * 72 + cn] };
                mma8(acc[0][nm], af[0], bf);
                mma8(acc[1][nm], af[1], bf);
            }
        }
    }
    #pragma unroll
    for (int mm = 0; mm < 2; mm++) {
        #pragma unroll
        for (int nm = 0; nm < 4; nm++) {
            int r = m0 + wm * 32 + mm * 16 + (lane >> 2);
            int c = n0 + wn * 32 + nm * 8 + 2 * (lane & 3);
            float2 xr0 = *(const float2*)&x[(size_t)r * D_DIM + c];
            float2 xr1 = *(const float2*)&x[(size_t)(r + 8) * D_DIM + c];
            float b0 = bias[c], b1 = bias[c + 1];
            *(float2*)&out[(size_t)r * D_DIM + c] =
                make_float2(acc[mm][nm][0] + b0 + xr0.x, acc[mm][nm][1] + b1 + xr0.y);
            *(float2*)&out[(size_t)(r + 8) * D_DIM + c] =
                make_float2(acc[mm][nm][2] + b0 + xr1.x, acc[mm][nm][3] + b1 + xr1.y);
        }
    }
}

// ---------------------------------------------------------------------------
// Launcher
// ---------------------------------------------------------------------------
extern "C" void kernel_launch(void* const* d_in, const int* in_sizes, int n_in,
                              void* d_out, int out_size) {
    const float* x    = (const float*)d_in[0];
    const float* uvqk = (const float*)d_in[1];
    const float* o_w  = (const float*)d_in[2];
    const float* o_b  = (const float*)d_in[3];
    const float* ts_w = (const float*)d_in[4];
    const int*   ts   = (const int*)d_in[5];
    float* out = (float*)d_out;

    ln_x_kernel<<<T_TOK / 8, 256>>>(x);
    gemm_uvqk_mma<<<dim3(HID / 64, T_TOK / 128), 256>>>(uvqk);
    attn_mma<<<dim3(100, 4), 256>>>(ts, ts_w);
    oin_kernel<<<T_TOK / 8, 256>>>();
    gemm_out_mma<<<dim3(D_DIM / 64, T_TOK / 128), 256>>>(o_w, o_b, x, out);
}

// round 9
// speedup vs baseline: 1.6664x; 1.0766x over previous
#include <cuda_runtime.h>
#include <cuda_bf16.h>
#include <cuda_fp16.h>
#include <math.h>

// ---------------------------------------------------------------------------
// Problem constants
// ---------------------------------------------------------------------------
#define T_TOK   6400
#define D_DIM   512
#define HID     1024
#define N_SEQ   2048
#define EPS     1e-6f
#define INV_N   (1.0f/2048.0f)

__device__ __constant__ int c_off[5] = {0, 2048, 3584, 4608, 6400};
// (batch, qt) for 64-row q-tiles, exact qt-descending order (longest first).
__device__ __constant__ unsigned char c_ord[100][2] = {
 {0,31},{0,30},{0,29},{0,28},
 {0,27},{3,27},{0,26},{3,26},{0,25},{3,25},{0,24},{3,24},
 {0,23},{1,23},{3,23},{0,22},{1,22},{3,22},{0,21},{1,21},{3,21},
 {0,20},{1,20},{3,20},{0,19},{1,19},{3,19},{0,18},{1,18},{3,18},
 {0,17},{1,17},{3,17},{0,16},{1,16},{3,16},
 {0,15},{1,15},{2,15},{3,15},{0,14},{1,14},{2,14},{3,14},
 {0,13},{1,13},{2,13},{3,13},{0,12},{1,12},{2,12},{3,12},
 {0,11},{1,11},{2,11},{3,11},{0,10},{1,10},{2,10},{3,10},
 {0,9},{1,9},{2,9},{3,9},{0,8},{1,8},{2,8},{3,8},
 {0,7},{1,7},{2,7},{3,7},{0,6},{1,6},{2,6},{3,6},
 {0,5},{1,5},{2,5},{3,5},{0,4},{1,4},{2,4},{3,4},
 {0,3},{1,3},{2,3},{3,3},{0,2},{1,2},{2,2},{3,2},
 {0,1},{1,1},{2,1},{3,1},{0,0},{1,0},{2,0},{3,0}};

// ---------------------------------------------------------------------------
// Scratch
// ---------------------------------------------------------------------------
__device__ float g_xn  [T_TOK * D_DIM];
__device__ float g_h   [T_TOK * HID];     // u|v|q|k
__device__ float g_attn[T_TOK * 256];
__device__ float g_oin [T_TOK * 256];

// ---------------------------------------------------------------------------
// helpers
// ---------------------------------------------------------------------------
__device__ __forceinline__ void mma16(float* c, const unsigned* a, unsigned b0, unsigned b1) {
    asm volatile(
      "mma.sync.aligned.m16n8k16.row.col.f32.f16.f16.f32 "
      "{%0,%1,%2,%3}, {%4,%5,%6,%7}, {%8,%9}, {%0,%1,%2,%3};"
      : "+f"(c[0]), "+f"(c[1]), "+f"(c[2]), "+f"(c[3])
      : "r"(a[0]), "r"(a[1]), "r"(a[2]), "r"(a[3]), "r"(b0), "r"(b1));
}
__device__ __forceinline__ void ldsm4(unsigned* r, unsigned addr) {
    asm volatile("ldmatrix.sync.aligned.m8n8.x4.shared.b16 {%0,%1,%2,%3}, [%4];"
        : "=r"(r[0]), "=r"(r[1]), "=r"(r[2]), "=r"(r[3]) : "r"(addr));
}
__device__ __forceinline__ void ldsm4t(unsigned* r, unsigned addr) {
    asm volatile("ldmatrix.sync.aligned.m8n8.x4.trans.shared.b16 {%0,%1,%2,%3}, [%4];"
        : "=r"(r[0]), "=r"(r[1]), "=r"(r[2]), "=r"(r[3]) : "r"(addr));
}
__device__ __forceinline__ unsigned packh2(float x, float y) {
    __half2 h = __floats2half2_rn(x, y);
    return *(unsigned*)&h;
}
__device__ __forceinline__ float silu_f(float s) {
    return s * __fdividef(1.0f, 1.0f + __expf(-s));
}

// ---------------------------------------------------------------------------
// Kernel 1: LayerNorm over D=512, warp-per-token
// ---------------------------------------------------------------------------
__global__ void ln_x_kernel(const float* __restrict__ x) {
    int t = blockIdx.x * 8 + (threadIdx.x >> 5);
    int lane = threadIdx.x & 31;
    const float* row = x + (size_t)t * D_DIM + lane * 4;
    float4 v[4];
    #pragma unroll
    for (int w = 0; w < 4; w++) v[w] = *(const float4*)(row + w * 128);
    float s = 0.f, q = 0.f;
    #pragma unroll
    for (int w = 0; w < 4; w++) {
        s += v[w].x + v[w].y + v[w].z + v[w].w;
        q += v[w].x*v[w].x + v[w].y*v[w].y + v[w].z*v[w].z + v[w].w*v[w].w;
    }
    #pragma unroll
    for (int o = 16; o > 0; o >>= 1) {
        s += __shfl_xor_sync(0xffffffffu, s, o);
        q += __shfl_xor_sync(0xffffffffu, q, o);
    }
    float m = s * (1.0f / D_DIM);
    float r = rsqrtf(q * (1.0f / D_DIM) - m * m + EPS);
    float* dst = g_xn + (size_t)t * D_DIM + lane * 4;
    #pragma unroll
    for (int w = 0; w < 4; w++) {
        *(float4*)(dst + w * 128) = make_float4(
            (v[w].x - m) * r, (v[w].y - m) * r, (v[w].z - m) * r, (v[w].w - m) * r);
    }
}

// ---------------------------------------------------------------------------
// Kernel 2: h = silu(xn @ uvqk)  [6400,512]@[512,1024]  -- fp16 mma + ldmatrix
// BM=128 BN=64 BK=32, 8 warps (4x2), warp tile 32x32
// ---------------------------------------------------------------------------
__global__ void gemm_uvqk_h(const float* __restrict__ W) {
    __shared__ __align__(16) __half Ah[128 * 40];   // [m][k] stride 40
    __shared__ __align__(16) __half Bh[32 * 72];    // [k][n] stride 72
    int tid = threadIdx.x, lane = tid & 31, warp = tid >> 5;
    int wm = warp >> 1, wn = warp & 1;
    int m0 = blockIdx.y * 128, n0 = blockIdx.x * 64;

    float acc[2][4][4];
    #pragma unroll
    for (int a = 0; a < 2; a++)
        #pragma unroll
        for (int b = 0; b < 4; b++)
            #pragma unroll
            for (int c = 0; c < 4; c++) acc[a][b][c] = 0.f;

    int lr = tid >> 1, lk = (tid & 1) << 4;       // A: row 0..127, k-off 0/16
    int br = tid >> 3, bc = (tid & 7) << 3;       // B: k-row 0..31, n-off 0..56
    const float* Ap = g_xn + (size_t)(m0 + lr) * D_DIM + lk;

    unsigned abase = (unsigned)__cvta_generic_to_shared(Ah);
    unsigned bbase = (unsigned)__cvta_generic_to_shared(Bh);
    int a_row = lane & 15, a_col = (lane >> 4) * 8;              // A frag (non-trans)
    int v_row = (lane & 7) + ((lane >> 3) & 1) * 8;              // B frag (trans, [k][n])
    int v_col = (lane >> 4) * 8;

    for (int k0 = 0; k0 < D_DIM; k0 += 32) {
        float4 av[4];
        #pragma unroll
        for (int j = 0; j < 4; j++) av[j] = *(const float4*)(Ap + k0 + 4 * j);
        float4 w0 = *(const float4*)&W[(size_t)(k0 + br) * HID + n0 + bc];
        float4 w1 = *(const float4*)&W[(size_t)(k0 + br) * HID + n0 + bc + 4];
        __syncthreads();
        *(uint4*)(Ah + lr * 40 + lk) = make_uint4(
            packh2(av[0].x, av[0].y), packh2(av[0].z, av[0].w),
            packh2(av[1].x, av[1].y), packh2(av[1].z, av[1].w));
        *(uint4*)(Ah + lr * 40 + lk + 8) = make_uint4(
            packh2(av[2].x, av[2].y), packh2(av[2].z, av[2].w),
            packh2(av[3].x, av[3].y), packh2(av[3].z, av[3].w));
        *(uint4*)(Bh + br * 72 + bc) = make_uint4(
            packh2(w0.x, w0.y), packh2(w0.z, w0.w),
            packh2(w1.x, w1.y), packh2(w1.z, w1.w));
        __syncthreads();
        #pragma unroll
        for (int kc = 0; kc < 32; kc += 16) {
            unsigned af[2][4];
            ldsm4(af[0], abase + ((wm * 32 + a_row) * 40 + kc + a_col) * 2);
            ldsm4(af[1], abase + ((wm * 32 + 16 + a_row) * 40 + kc + a_col) * 2);
            #pragma unroll
            for (int n16 = 0; n16 < 2; n16++) {
                unsigned bf[4];
                ldsm4t(bf, bbase + ((kc + v_row) * 72 + wn * 32 + n16 * 16 + v_col) * 2);
                mma16(acc[0][n16 * 2],     af[0], bf[0], bf[1]);
                mma16(acc[0][n16 * 2 + 1], af[0], bf[2], bf[3]);
                mma16(acc[1][n16 * 2],     af[1], bf[0], bf[1]);
                mma16(acc[1][n16 * 2 + 1], af[1], bf[2], bf[3]);
            }
        }
    }
    int gid = lane >> 2, tig = lane & 3;
    #pragma unroll
    for (int mm = 0; mm < 2; mm++) {
        #pragma unroll
        for (int nm = 0; nm < 4; nm++) {
            int r = m0 + wm * 32 + mm * 16 + gid;
            int c = n0 + wn * 32 + nm * 8 + 2 * tig;
            *(float2*)&g_h[(size_t)r * HID + c] =
                make_float2(silu_f(acc[mm][nm][0]), silu_f(acc[mm][nm][1]));
            *(float2*)&g_h[(size_t)(r + 8) * HID + c] =
                make_float2(silu_f(acc[mm][nm][2]), silu_f(acc[mm][nm][3]));
        }
    }
}

// ---------------------------------------------------------------------------
// Kernel 3: jagged causal attention, fp16 mma + ldmatrix (unchanged from R8)
// ---------------------------------------------------------------------------
#define HS 72
#define SM_Q  0
#define SM_K  9216
#define SM_V  18432
#define SM_TW 27648
#define SM_TH 28176
#define SM_TQ 28240
#define SM_TK 28496
#define SM_TOT 28752

__global__ void __launch_bounds__(256, 2)
attn_mma(const int* __restrict__ ts, const float* __restrict__ tsw) {
    __shared__ __align__(16) unsigned char smb[SM_TOT];
    __half* Qh = (__half*)(smb + SM_Q);
    __half* Kh = (__half*)(smb + SM_K);
    __half* Vh = (__half*)(smb + SM_V);
    float*  red = (float*)smb;
    float*  tw  = (float*)(smb + SM_TW);
    float*  thf = (float*)(smb + SM_TH);
    int*    tqs = (int*)(smb + SM_TQ);
    int*    tks = (int*)(smb + SM_TK);

    int b  = c_ord[blockIdx.x][0];
    int qt = c_ord[blockIdx.x][1];
    int head = blockIdx.y;
    int tok0 = c_off[b] + qt * 64;

    int tid = threadIdx.x, lane = tid & 31, warp = tid >> 5;
    int wm = warp >> 1, wn = warp & 1;
    int i0 = wm * 16;
    int gid = lane >> 2, tig = lane & 3;

    unsigned qbase = (unsigned)__cvta_generic_to_shared(Qh);
    unsigned kbase = (unsigned)__cvta_generic_to_shared(Kh);
    unsigned vbase = (unsigned)__cvta_generic_to_shared(Vh);

    const float* qb = g_h + 512 + head * 64;
    for (int i = tid; i < 1024; i += 256) {
        int r = i >> 4, c = (i & 15) << 2;
        float4 v = *(const float4*)&qb[(size_t)(tok0 + r) * HID + c];
        *(uint2*)(Qh + r * HS + c) =
            make_uint2(packh2(v.x, v.y), packh2(v.z, v.w));
    }
    for (int i = tid; i < 129; i += 256) tw[i] = tsw[i];
    if (tid < 64) tqs[tid] = ts[b * N_SEQ + qt * 64 + tid];
    if (tid < 15) {
        if (tid == 0) thf[0] = 0.f;
        else {
            int k = tid;
            int t = (int)(expf((float)k)) - 9;
            if (t < 1) t = 1;
            while (t > 1 && log1pf((float)(t - 1)) >= (float)k) --t;
            while (log1pf((float)t) < (float)k) ++t;
            thf[k] = (float)t;
        }
    }
    __syncthreads();
    float th[14];
    #pragma unroll
    for (int k = 0; k < 14; k++) th[k] = thf[k + 1];
    int tq0 = tqs[i0 + gid];
    int tq8 = tqs[i0 + gid + 8];

    float accO[8][4];
    #pragma unroll
    for (int t = 0; t < 8; t++)
        #pragma unroll
        for (int c = 0; c < 4; c++) accO[t][c] = 0.f;

    const float* kb = g_h + 768 + head * 64;
    const float* vb = g_h + 256 + head * 64;

    int a_row = lane & 15, a_col = (lane >> 4) * 8;
    int b_row = ((lane >> 4) * 8) + (lane & 7);
    int b_col = ((lane >> 3) & 1) * 8;
    int v_row = (lane & 7) + ((lane >> 3) & 1) * 8;
    int v_col = (lane >> 4) * 8;

    for (int jt = 0; jt <= qt; ++jt) {
        int ktok = c_off[b] + jt * 64;
        __syncthreads();
        for (int i = tid; i < 1024; i += 256) {
            int r = i >> 4, c = (i & 15) << 2;
            float4 kv = *(const float4*)&kb[(size_t)(ktok + r) * HID + c];
            float4 vv = *(const float4*)&vb[(size_t)(ktok + r) * HID + c];
            *(uint2*)(Kh + r * HS + c) =
                make_uint2(packh2(kv.x, kv.y), packh2(kv.z, kv.w));
            *(uint2*)(Vh + r * HS + c) =
                make_uint2(packh2(vv.x, vv.y), packh2(vv.z, vv.w));
        }
        if (tid < 64) tks[tid] = ts[b * N_SEQ + jt * 64 + tid];
        __syncthreads();

        float accS[4][4];
        #pragma unroll
        for (int a = 0; a < 4; a++)
            #pragma unroll
            for (int c = 0; c < 4; c++) accS[a][c] = 0.f;
        #pragma unroll
        for (int kc = 0; kc < 4; kc++) {
            int d0 = kc * 16;
            unsigned af[4];
            ldsm4(af, qbase + ((i0 + a_row) * HS + d0 + a_col) * 2);
            #pragma unroll
            for (int hh = 0; hh < 2; hh++) {
                int j0 = wn * 32 + hh * 16;
                unsigned bf[4];
                ldsm4(bf, kbase + ((j0 + b_row) * HS + d0 + b_col) * 2);
                mma16(accS[hh * 2],     af, bf[0], bf[1]);
                mma16(accS[hh * 2 + 1], af, bf[2], bf[3]);
            }
        }

        bool full = (jt < qt);
        #pragma unroll
        for (int nm = 0; nm < 4; nm++) {
            #pragma unroll
            for (int e = 0; e < 4; e++) {
                int i = i0 + gid + ((e & 2) ? 8 : 0);
                int j = wn * 32 + nm * 8 + tig * 2 + (e & 1);
                float p = 0.f;
                if (full || j <= i) {
                    int tq = (e & 2) ? tq8 : tq0;
                    float fd = fabsf((float)(tq - tks[j]));
                    int bkt = 0;
                    #pragma unroll
                    for (int k = 0; k < 14; k++) bkt += (fd >= th[k]) ? 1 : 0;
                    p = silu_f(accS[nm][e] + tw[bkt]);
                }
                accS[nm][e] = p;
            }
        }

        unsigned pa[2][4];
        #pragma unroll
        for (int kc = 0; kc < 2; kc++) {
            pa[kc][0] = packh2(accS[2*kc][0],     accS[2*kc][1]);
            pa[kc][1] = packh2(accS[2*kc][2],     accS[2*kc][3]);
            pa[kc][2] = packh2(accS[2*kc+1][0],   accS[2*kc+1][1]);
            pa[kc][3] = packh2(accS[2*kc+1][2],   accS[2*kc+1][3]);
        }

        #pragma unroll
        for (int kc = 0; kc < 2; kc++) {
            int jc = wn * 32 + kc * 16;
            #pragma unroll
            for (int lt = 0; lt < 4; lt++) {
                int l0 = lt * 16;
                unsigned bf[4];
                ldsm4t(bf, vbase + ((jc + v_row) * HS + l0 + v_col) * 2);
                mma16(accO[lt * 2],     pa[kc], bf[0], bf[1]);
                mma16(accO[lt * 2 + 1], pa[kc], bf[2], bf[3]);
            }
        }
    }

    __syncthreads();
    if (wn == 1) {
        #pragma unroll
        for (int t = 0; t < 8; t++)
            #pragma unroll
            for (int e = 0; e < 4; e++)
                red[((t * 4 + e) * 4 + wm) * 32 + lane] = accO[t][e];
    }
    __syncthreads();
    if (wn == 0) {
        #pragma unroll
        for (int t = 0; t < 8; t++)
            #pragma unroll
            for (int e = 0; e < 4; e++)
                accO[t][e] += red[((t * 4 + e) * 4 + wm) * 32 + lane];
        #pragma unroll
        for (int nt = 0; nt < 8; nt++) {
            int i = tok0 + i0 + gid;
            int l = head * 64 + nt * 8 + tig * 2;
            *(float2*)&g_attn[(size_t)i * 256 + l] =
                make_float2(accO[nt][0] * INV_N, accO[nt][1] * INV_N);
            *(float2*)&g_attn[(size_t)(i + 8) * 256 + l] =
                make_float2(accO[nt][2] * INV_N, accO[nt][3] * INV_N);
        }
    }
}

// ---------------------------------------------------------------------------
// Kernel 4: oin = u * LN(attn), warp-per-token
// ---------------------------------------------------------------------------
__global__ void oin_kernel() {
    int t = blockIdx.x * 8 + (threadIdx.x >> 5);
    int lane = threadIdx.x & 31;
    const float* row = g_attn + (size_t)t * 256 + lane * 4;
    float4 a0 = *(const float4*)(row);
    float4 a1 = *(const float4*)(row + 128);
    float s = a0.x + a0.y + a0.z + a0.w + a1.x + a1.y + a1.z + a1.w;
    float q = a0.x*a0.x + a0.y*a0.y + a0.z*a0.z + a0.w*a0.w
            + a1.x*a1.x + a1.y*a1.y + a1.z*a1.z + a1.w*a1.w;
    #pragma unroll
    for (int o = 16; o > 0; o >>= 1) {
        s += __shfl_xor_sync(0xffffffffu, s, o);
        q += __shfl_xor_sync(0xffffffffu, q, o);
    }
    float m = s * (1.0f / 256.0f);
    float r = rsqrtf(q * (1.0f / 256.0f) - m * m + EPS);
    const float* up = g_h + (size_t)t * HID + lane * 4;
    float4 u0 = *(const float4*)(up);
    float4 u1 = *(const float4*)(up + 128);
    float* dst = g_oin + (size_t)t * 256 + lane * 4;
    *(float4*)(dst) = make_float4(u0.x * (a0.x - m) * r, u0.y * (a0.y - m) * r,
                                  u0.z * (a0.z - m) * r, u0.w * (a0.w - m) * r);
    *(float4*)(dst + 128) = make_float4(u1.x * (a1.x - m) * r, u1.y * (a1.y - m) * r,
                                        u1.z * (a1.z - m) * r, u1.w * (a1.w - m) * r);
}

// ---------------------------------------------------------------------------
// Kernel 5: out = oin @ o_w^T + o_b + x  [6400,256]@[256,512] -- fp16 mma
// o_w is [n][k] row-major -> non-trans ldmatrix (K-style B fragments)
// ---------------------------------------------------------------------------
__global__ void gemm_out_h(const float* __restrict__ Wo,
                           const float* __restrict__ bias,
                           const float* __restrict__ x,
                           float* __restrict__ out) {
    __shared__ __align__(16) __half Ah[128 * 40];   // [m][k] stride 40
    __shared__ __align__(16) __half Wh[64 * 40];    // [n][k] stride 40
    int tid = threadIdx.x, lane = tid & 31, warp = tid >> 5;
    int wm = warp >> 1, wn = warp & 1;
    int m0 = blockIdx.y * 128, n0 = blockIdx.x * 64;

    float acc[2][4][4];
    #pragma unroll
    for (int a = 0; a < 2; a++)
        #pragma unroll
        for (int b = 0; b < 4; b++)
            #pragma unroll
            for (int c = 0; c < 4; c++) acc[a][b][c] = 0.f;

    int lr = tid >> 1, lk = (tid & 1) << 4;
    int wr = tid >> 2, wc = (tid & 3) << 3;
    const float* Ap = g_oin + (size_t)(m0 + lr) * 256 + lk;
    const float* Wp = Wo + (size_t)(n0 + wr) * 256 + wc;

    unsigned abase = (unsigned)__cvta_generic_to_shared(Ah);
    unsigned wbase = (unsigned)__cvta_generic_to_shared(Wh);
    int a_row = lane & 15, a_col = (lane >> 4) * 8;
    int b_row = ((lane >> 4) * 8) + (lane & 7);
    int b_col = ((lane >> 3) & 1) * 8;

    for (int k0 = 0; k0 < 256; k0 += 32) {
        float4 av[4];
        #pragma unroll
        for (int j = 0; j < 4; j++) av[j] = *(const float4*)(Ap + k0 + 4 * j);
        float4 w0 = *(const float4*)(Wp + k0);
        float4 w1 = *(const float4*)(Wp + k0 + 4);
        __syncthreads();
        *(uint4*)(Ah + lr * 40 + lk) = make_uint4(
            packh2(av[0].x, av[0].y), packh2(av[0].z, av[0].w),
            packh2(av[1].x, av[1].y), packh2(av[1].z, av[1].w));
        *(uint4*)(Ah + lr * 40 + lk + 8) = make_uint4(
            packh2(av[2].x, av[2].y), packh2(av[2].z, av[2].w),
            packh2(av[3].x, av[3].y), packh2(av[3].z, av[3].w));
        *(uint4*)(Wh + wr * 40 + wc) = make_uint4(
            packh2(w0.x, w0.y), packh2(w0.z, w0.w),
            packh2(w1.x, w1.y), packh2(w1.z, w1.w));
        __syncthreads();
        #pragma unroll
        for (int kc = 0; kc < 32; kc += 16) {
            unsigned af[2][4];
            ldsm4(af[0], abase + ((wm * 32 + a_row) * 40 + kc + a_col) * 2);
            ldsm4(af[1], abase + ((wm * 32 + 16 + a_row) * 40 + kc + a_col) * 2);
            #pragma unroll
            for (int n16 = 0; n16 < 2; n16++) {
                unsigned bf[4];
                ldsm4(bf, wbase + ((wn * 32 + n16 * 16 + b_row) * 40 + kc + b_col) * 2);
                mma16(acc[0][n16 * 2],     af[0], bf[0], bf[1]);
                mma16(acc[0][n16 * 2 + 1], af[0], bf[2], bf[3]);
                mma16(acc[1][n16 * 2],     af[1], bf[0], bf[1]);
                mma16(acc[1][n16 * 2 + 1], af[1], bf[2], bf[3]);
            }
        }
    }
    int gid = lane >> 2, tig = lane & 3;
    #pragma unroll
    for (int mm = 0; mm < 2; mm++) {
        #pragma unroll
        for (int nm = 0; nm < 4; nm++) {
            int r = m0 + wm * 32 + mm * 16 + gid;
            int c = n0 + wn * 32 + nm * 8 + 2 * tig;
            float2 xr0 = *(const float2*)&x[(size_t)r * D_DIM + c];
            float2 xr1 = *(const float2*)&x[(size_t)(r + 8) * D_DIM + c];
            float b0 = bias[c], b1 = bias[c + 1];
            *(float2*)&out[(size_t)r * D_DIM + c] =
                make_float2(acc[mm][nm][0] + b0 + xr0.x, acc[mm][nm][1] + b1 + xr0.y);
            *(float2*)&out[(size_t)(r + 8) * D_DIM + c] =
                make_float2(acc[mm][nm][2] + b0 + xr1.x, acc[mm][nm][3] + b1 + xr1.y);
        }
    }
}

// ---------------------------------------------------------------------------
// Launcher
// ---------------------------------------------------------------------------
extern "C" void kernel_launch(void* const* d_in, const int* in_sizes, int n_in,
                              void* d_out, int out_size) {
    const float* x    = (const float*)d_in[0];
    const float* uvqk = (const float*)d_in[1];
    const float* o_w  = (const float*)d_in[2];
    const float* o_b  = (const float*)d_in[3];
    const float* ts_w = (const float*)d_in[4];
    const int*   ts   = (const int*)d_in[5];
    float* out = (float*)d_out;

    ln_x_kernel<<<T_TOK / 8, 256>>>(x);
    gemm_uvqk_h<<<dim3(HID / 64, T_TOK / 128), 256>>>(uvqk);
    attn_mma<<<dim3(100, 4), 256>>>(ts, ts_w);
    oin_kernel<<<T_TOK / 8, 256>>>();
    gemm_out_h<<<dim3(D_DIM / 64, T_TOK / 128), 256>>>(o_w, o_b, x, out);
}

// round 10
// speedup vs baseline: 1.9896x; 1.1939x over previous
#include <cuda_runtime.h>
#include <cuda_bf16.h>
#include <cuda_fp16.h>
#include <math.h>

// ---------------------------------------------------------------------------
// Problem constants
// ---------------------------------------------------------------------------
#define T_TOK   6400
#define D_DIM   512
#define HID     1024
#define N_SEQ   2048
#define EPS     1e-6f
#define INV_N   (1.0f/2048.0f)

__device__ __constant__ int c_off[5] = {0, 2048, 3584, 4608, 6400};
// (batch, qt) for 64-row q-tiles, exact qt-descending order (longest first).
__device__ __constant__ unsigned char c_ord[100][2] = {
 {0,31},{0,30},{0,29},{0,28},
 {0,27},{3,27},{0,26},{3,26},{0,25},{3,25},{0,24},{3,24},
 {0,23},{1,23},{3,23},{0,22},{1,22},{3,22},{0,21},{1,21},{3,21},
 {0,20},{1,20},{3,20},{0,19},{1,19},{3,19},{0,18},{1,18},{3,18},
 {0,17},{1,17},{3,17},{0,16},{1,16},{3,16},
 {0,15},{1,15},{2,15},{3,15},{0,14},{1,14},{2,14},{3,14},
 {0,13},{1,13},{2,13},{3,13},{0,12},{1,12},{2,12},{3,12},
 {0,11},{1,11},{2,11},{3,11},{0,10},{1,10},{2,10},{3,10},
 {0,9},{1,9},{2,9},{3,9},{0,8},{1,8},{2,8},{3,8},
 {0,7},{1,7},{2,7},{3,7},{0,6},{1,6},{2,6},{3,6},
 {0,5},{1,5},{2,5},{3,5},{0,4},{1,4},{2,4},{3,4},
 {0,3},{1,3},{2,3},{3,3},{0,2},{1,2},{2,2},{3,2},
 {0,1},{1,1},{2,1},{3,1},{0,0},{1,0},{2,0},{3,0}};

// ---------------------------------------------------------------------------
// Scratch
// ---------------------------------------------------------------------------
__device__ float  g_xn  [T_TOK * D_DIM];
__device__ float  g_h   [T_TOK * HID];     // only u slice (cols 0..255) consumed
__device__ __half g_qh  [T_TOK * 256];     // q, fp16, [t][head*64+d]
__device__ __half g_kh  [T_TOK * 256];     // k
__device__ __half g_vh  [T_TOK * 256];     // v
__device__ float  g_attn[T_TOK * 256];
__device__ float  g_oin [T_TOK * 256];

// ---------------------------------------------------------------------------
// helpers
// ---------------------------------------------------------------------------
__device__ __forceinline__ void mma16(float* c, const unsigned* a, unsigned b0, unsigned b1) {
    asm volatile(
      "mma.sync.aligned.m16n8k16.row.col.f32.f16.f16.f32 "
      "{%0,%1,%2,%3}, {%4,%5,%6,%7}, {%8,%9}, {%0,%1,%2,%3};"
      : "+f"(c[0]), "+f"(c[1]), "+f"(c[2]), "+f"(c[3])
      : "r"(a[0]), "r"(a[1]), "r"(a[2]), "r"(a[3]), "r"(b0), "r"(b1));
}
__device__ __forceinline__ void ldsm4(unsigned* r, unsigned addr) {
    asm volatile("ldmatrix.sync.aligned.m8n8.x4.shared.b16 {%0,%1,%2,%3}, [%4];"
        : "=r"(r[0]), "=r"(r[1]), "=r"(r[2]), "=r"(r[3]) : "r"(addr));
}
__device__ __forceinline__ void ldsm4t(unsigned* r, unsigned addr) {
    asm volatile("ldmatrix.sync.aligned.m8n8.x4.trans.shared.b16 {%0,%1,%2,%3}, [%4];"
        : "=r"(r[0]), "=r"(r[1]), "=r"(r[2]), "=r"(r[3]) : "r"(addr));
}
__device__ __forceinline__ void cpa16(unsigned saddr, const void* g) {
    asm volatile("cp.async.ca.shared.global [%0], [%1], 16;" :: "r"(saddr), "l"(g));
}
__device__ __forceinline__ unsigned packh2(float x, float y) {
    __half2 h = __floats2half2_rn(x, y);
    return *(unsigned*)&h;
}
__device__ __forceinline__ float silu_f(float s) {
    return s * __fdividef(1.0f, 1.0f + __expf(-s));
}

// ---------------------------------------------------------------------------
// Kernel 1: LayerNorm over D=512, warp-per-token
// ---------------------------------------------------------------------------
__global__ void ln_x_kernel(const float* __restrict__ x) {
    int t = blockIdx.x * 8 + (threadIdx.x >> 5);
    int lane = threadIdx.x & 31;
    const float* row = x + (size_t)t * D_DIM + lane * 4;
    float4 v[4];
    #pragma unroll
    for (int w = 0; w < 4; w++) v[w] = *(const float4*)(row + w * 128);
    float s = 0.f, q = 0.f;
    #pragma unroll
    for (int w = 0; w < 4; w++) {
        s += v[w].x + v[w].y + v[w].z + v[w].w;
        q += v[w].x*v[w].x + v[w].y*v[w].y + v[w].z*v[w].z + v[w].w*v[w].w;
    }
    #pragma unroll
    for (int o = 16; o > 0; o >>= 1) {
        s += __shfl_xor_sync(0xffffffffu, s, o);
        q += __shfl_xor_sync(0xffffffffu, q, o);
    }
    float m = s * (1.0f / D_DIM);
    float r = rsqrtf(q * (1.0f / D_DIM) - m * m + EPS);
    float* dst = g_xn + (size_t)t * D_DIM + lane * 4;
    #pragma unroll
    for (int w = 0; w < 4; w++) {
        *(float4*)(dst + w * 128) = make_float4(
            (v[w].x - m) * r, (v[w].y - m) * r, (v[w].z - m) * r, (v[w].w - m) * r);
    }
}

// ---------------------------------------------------------------------------
// Kernel 2: h = silu(xn @ uvqk)  -- fp16 mma + ldmatrix
// epilogue: u (cols 0..255) -> g_h fp32 ; v/q/k -> g_vh/g_qh/g_kh fp16
// ---------------------------------------------------------------------------
__global__ void gemm_uvqk_h(const float* __restrict__ W) {
    __shared__ __align__(16) __half Ah[128 * 40];   // [m][k] stride 40
    __shared__ __align__(16) __half Bh[32 * 72];    // [k][n] stride 72
    int tid = threadIdx.x, lane = tid & 31, warp = tid >> 5;
    int wm = warp >> 1, wn = warp & 1;
    int m0 = blockIdx.y * 128, n0 = blockIdx.x * 64;

    float acc[2][4][4];
    #pragma unroll
    for (int a = 0; a < 2; a++)
        #pragma unroll
        for (int b = 0; b < 4; b++)
            #pragma unroll
            for (int c = 0; c < 4; c++) acc[a][b][c] = 0.f;

    int lr = tid >> 1, lk = (tid & 1) << 4;
    int br = tid >> 3, bc = (tid & 7) << 3;
    const float* Ap = g_xn + (size_t)(m0 + lr) * D_DIM + lk;

    unsigned abase = (unsigned)__cvta_generic_to_shared(Ah);
    unsigned bbase = (unsigned)__cvta_generic_to_shared(Bh);
    int a_row = lane & 15, a_col = (lane >> 4) * 8;
    int v_row = (lane & 7) + ((lane >> 3) & 1) * 8;
    int v_col = (lane >> 4) * 8;

    for (int k0 = 0; k0 < D_DIM; k0 += 32) {
        float4 av[4];
        #pragma unroll
        for (int j = 0; j < 4; j++) av[j] = *(const float4*)(Ap + k0 + 4 * j);
        float4 w0 = *(const float4*)&W[(size_t)(k0 + br) * HID + n0 + bc];
        float4 w1 = *(const float4*)&W[(size_t)(k0 + br) * HID + n0 + bc + 4];
        __syncthreads();
        *(uint4*)(Ah + lr * 40 + lk) = make_uint4(
            packh2(av[0].x, av[0].y), packh2(av[0].z, av[0].w),
            packh2(av[1].x, av[1].y), packh2(av[1].z, av[1].w));
        *(uint4*)(Ah + lr * 40 + lk + 8) = make_uint4(
            packh2(av[2].x, av[2].y), packh2(av[2].z, av[2].w),
            packh2(av[3].x, av[3].y), packh2(av[3].z, av[3].w));
        *(uint4*)(Bh + br * 72 + bc) = make_uint4(
            packh2(w0.x, w0.y), packh2(w0.z, w0.w),
            packh2(w1.x, w1.y), packh2(w1.z, w1.w));
        __syncthreads();
        #pragma unroll
        for (int kc = 0; kc < 32; kc += 16) {
            unsigned af[2][4];
            ldsm4(af[0], abase + ((wm * 32 + a_row) * 40 + kc + a_col) * 2);
            ldsm4(af[1], abase + ((wm * 32 + 16 + a_row) * 40 + kc + a_col) * 2);
            #pragma unroll
            for (int n16 = 0; n16 < 2; n16++) {
                unsigned bf[4];
                ldsm4t(bf, bbase + ((kc + v_row) * 72 + wn * 32 + n16 * 16 + v_col) * 2);
                mma16(acc[0][n16 * 2],     af[0], bf[0], bf[1]);
                mma16(acc[0][n16 * 2 + 1], af[0], bf[2], bf[3]);
                mma16(acc[1][n16 * 2],     af[1], bf[0], bf[1]);
                mma16(acc[1][n16 * 2 + 1], af[1], bf[2], bf[3]);
            }
        }
    }
    int gid = lane >> 2, tig = lane & 3;
    int seg = n0 >> 8;                       // 0=u 1=v 2=q 3=k (uniform per block)
    __half* segp = (seg == 1) ? g_vh : (seg == 2) ? g_qh : g_kh;
    #pragma unroll
    for (int mm = 0; mm < 2; mm++) {
        #pragma unroll
        for (int nm = 0; nm < 4; nm++) {
            int r = m0 + wm * 32 + mm * 16 + gid;
            float s0 = silu_f(acc[mm][nm][0]), s1 = silu_f(acc[mm][nm][1]);
            float s2 = silu_f(acc[mm][nm][2]), s3 = silu_f(acc[mm][nm][3]);
            if (seg == 0) {
                int c = n0 + wn * 32 + nm * 8 + 2 * tig;
                *(float2*)&g_h[(size_t)r * HID + c] = make_float2(s0, s1);
                *(float2*)&g_h[(size_t)(r + 8) * HID + c] = make_float2(s2, s3);
            } else {
                int c = (n0 & 255) + wn * 32 + nm * 8 + 2 * tig;
                *(unsigned*)&segp[(size_t)r * 256 + c] = packh2(s0, s1);
                *(unsigned*)&segp[(size_t)(r + 8) * 256 + c] = packh2(s2, s3);
            }
        }
    }
}

// ---------------------------------------------------------------------------
// Kernel 3: jagged causal attention, fp16 mma + ldmatrix + cp.async pipeline
// ---------------------------------------------------------------------------
#define HS 72
#define KV_B 9216                 // one K or V buffer (64*72 halves)
#define SM_Q  0
#define SM_K0 9216
#define SM_K1 18432
#define SM_V0 27648
#define SM_V1 36864
#define SM_TW 46080               // 132 floats
#define SM_TH 46608               // 16 floats
#define SM_TQ 46672               // 64 ints
#define SM_TK 46928               // 2*64 ints (double buffered)
#define SM_TOT 47440              // < 48KB static; red (16KB) aliases Q/K0

__global__ void __launch_bounds__(256, 2)
attn_mma(const int* __restrict__ ts, const float* __restrict__ tsw) {
    __shared__ __align__(16) unsigned char smb[SM_TOT];
    __half* Qh = (__half*)(smb + SM_Q);
    float*  red = (float*)smb;
    float*  tw  = (float*)(smb + SM_TW);
    float*  thf = (float*)(smb + SM_TH);
    int*    tqs = (int*)(smb + SM_TQ);
    int*    tkb = (int*)(smb + SM_TK);

    int b  = c_ord[blockIdx.x][0];
    int qt = c_ord[blockIdx.x][1];
    int head = blockIdx.y;
    int tok0 = c_off[b] + qt * 64;

    int tid = threadIdx.x, lane = tid & 31, warp = tid >> 5;
    int wm = warp >> 1, wn = warp & 1;
    int i0 = wm * 16;
    int gid = lane >> 2, tig = lane & 3;

    unsigned qbase  = (unsigned)__cvta_generic_to_shared(smb + SM_Q);
    unsigned kbase0 = (unsigned)__cvta_generic_to_shared(smb + SM_K0);
    unsigned vbase0 = (unsigned)__cvta_generic_to_shared(smb + SM_V0);

    const __half* qb = g_qh + head * 64;
    const __half* kb = g_kh + head * 64;
    const __half* vb = g_vh + head * 64;

    // stage Q (fp16 copy, 2 x uint4 per thread)
    #pragma unroll
    for (int it = 0; it < 2; it++) {
        int i = tid + it * 256;
        int r = i >> 3, c = (i & 7) << 3;
        *(uint4*)(Qh + r * HS + c) =
            *(const uint4*)(qb + (size_t)(tok0 + r) * 256 + c);
    }
    for (int i = tid; i < 129; i += 256) tw[i] = tsw[i];
    if (tid < 64) tqs[tid] = ts[b * N_SEQ + qt * 64 + tid];
    if (tid < 15) {
        if (tid == 0) thf[0] = 0.f;
        else {
            int k = tid;
            int t = (int)(expf((float)k)) - 9;
            if (t < 1) t = 1;
            while (t > 1 && log1pf((float)(t - 1)) >= (float)k) --t;
            while (log1pf((float)t) < (float)k) ++t;
            thf[k] = (float)t;
        }
    }

    // prologue: async-load K/V tile jt=0 into buffer 0
    {
        int ktok = c_off[b];
        #pragma unroll
        for (int it = 0; it < 2; it++) {
            int i = tid + it * 256;
            int r = i >> 3, c = (i & 7) << 3;
            unsigned soff = (unsigned)((r * HS + c) * 2);
            cpa16(kbase0 + soff, kb + (size_t)(ktok + r) * 256 + c);
            cpa16(vbase0 + soff, vb + (size_t)(ktok + r) * 256 + c);
        }
        asm volatile("cp.async.commit_group;");
        if (tid < 64) tkb[tid] = ts[b * N_SEQ + tid];
    }
    __syncthreads();
    float th[14];
    #pragma unroll
    for (int k = 0; k < 14; k++) th[k] = thf[k + 1];
    int tq0 = tqs[i0 + gid];
    int tq8 = tqs[i0 + gid + 8];

    float accO[8][4];
    #pragma unroll
    for (int t = 0; t < 8; t++)
        #pragma unroll
        for (int c = 0; c < 4; c++) accO[t][c] = 0.f;

    int a_row = lane & 15, a_col = (lane >> 4) * 8;
    int b_row = ((lane >> 4) * 8) + (lane & 7);
    int b_col = ((lane >> 3) & 1) * 8;
    int v_row = (lane & 7) + ((lane >> 3) & 1) * 8;
    int v_col = (lane >> 4) * 8;

    for (int jt = 0; jt <= qt; ++jt) {
        int bbuf = jt & 1;
        asm volatile("cp.async.wait_group 0;");
        __syncthreads();    // buffer bbuf loaded AND prior compute on bbuf^1 done

        // issue next tile into alternate buffer (overlaps with compute below)
        if (jt < qt) {
            int ktok = c_off[b] + (jt + 1) * 64;
            unsigned kb1 = kbase0 + (bbuf ^ 1) * KV_B;
            unsigned vb1 = vbase0 + (bbuf ^ 1) * KV_B;
            #pragma unroll
            for (int it = 0; it < 2; it++) {
                int i = tid + it * 256;
                int r = i >> 3, c = (i & 7) << 3;
                unsigned soff = (unsigned)((r * HS + c) * 2);
                cpa16(kb1 + soff, kb + (size_t)(ktok + r) * 256 + c);
                cpa16(vb1 + soff, vb + (size_t)(ktok + r) * 256 + c);
            }
            asm volatile("cp.async.commit_group;");
            if (tid < 64) tkb[(bbuf ^ 1) * 64 + tid] = ts[b * N_SEQ + (jt + 1) * 64 + tid];
        }

        unsigned kbase = kbase0 + bbuf * KV_B;
        unsigned vbase = vbase0 + bbuf * KV_B;
        const int* tks = tkb + bbuf * 64;

        // ---- S[i][j] = Q K^T
        float accS[4][4];
        #pragma unroll
        for (int a = 0; a < 4; a++)
            #pragma unroll
            for (int c = 0; c < 4; c++) accS[a][c] = 0.f;
        #pragma unroll
        for (int kc = 0; kc < 4; kc++) {
            int d0 = kc * 16;
            unsigned af[4];
            ldsm4(af, qbase + ((i0 + a_row) * HS + d0 + a_col) * 2);
            #pragma unroll
            for (int hh = 0; hh < 2; hh++) {
                int j0 = wn * 32 + hh * 16;
                unsigned bf[4];
                ldsm4(bf, kbase + ((j0 + b_row) * HS + d0 + b_col) * 2);
                mma16(accS[hh * 2],     af, bf[0], bf[1]);
                mma16(accS[hh * 2 + 1], af, bf[2], bf[3]);
            }
        }

        // ---- epilogue: bias + silu + causal
        bool full = (jt < qt);
        #pragma unroll
        for (int nm = 0; nm < 4; nm++) {
            #pragma unroll
            for (int e = 0; e < 4; e++) {
                int i = i0 + gid + ((e & 2) ? 8 : 0);
                int j = wn * 32 + nm * 8 + tig * 2 + (e & 1);
                float p = 0.f;
                if (full || j <= i) {
                    int tq = (e & 2) ? tq8 : tq0;
                    float fd = fabsf((float)(tq - tks[j]));
                    int bkt = 0;
                    #pragma unroll
                    for (int k = 0; k < 14; k++) bkt += (fd >= th[k]) ? 1 : 0;
                    p = silu_f(accS[nm][e] + tw[bkt]);
                }
                accS[nm][e] = p;
            }
        }

        // ---- C-frags -> A-frags in registers
        unsigned pa[2][4];
        #pragma unroll
        for (int kc = 0; kc < 2; kc++) {
            pa[kc][0] = packh2(accS[2*kc][0],     accS[2*kc][1]);
            pa[kc][1] = packh2(accS[2*kc][2],     accS[2*kc][3]);
            pa[kc][2] = packh2(accS[2*kc+1][0],   accS[2*kc+1][1]);
            pa[kc][3] = packh2(accS[2*kc+1][2],   accS[2*kc+1][3]);
        }

        // ---- O += P V
        #pragma unroll
        for (int kc = 0; kc < 2; kc++) {
            int jc = wn * 32 + kc * 16;
            #pragma unroll
            for (int lt = 0; lt < 4; lt++) {
                int l0 = lt * 16;
                unsigned bf[4];
                ldsm4t(bf, vbase + ((jc + v_row) * HS + l0 + v_col) * 2);
                mma16(accO[lt * 2],     pa[kc], bf[0], bf[1]);
                mma16(accO[lt * 2 + 1], pa[kc], bf[2], bf[3]);
            }
        }
    }

    // ---- cross-warp reduction of the two j-halves, then writeout
    __syncthreads();
    if (wn == 1) {
        #pragma unroll
        for (int t = 0; t < 8; t++)
            #pragma unroll
            for (int e = 0; e < 4; e++)
                red[((t * 4 + e) * 4 + wm) * 32 + lane] = accO[t][e];
    }
    __syncthreads();
    if (wn == 0) {
        #pragma unroll
        for (int t = 0; t < 8; t++)
            #pragma unroll
            for (int e = 0; e < 4; e++)
                accO[t][e] += red[((t * 4 + e) * 4 + wm) * 32 + lane];
        #pragma unroll
        for (int nt = 0; nt < 8; nt++) {
            int i = tok0 + i0 + gid;
            int l = head * 64 + nt * 8 + tig * 2;
            *(float2*)&g_attn[(size_t)i * 256 + l] =
                make_float2(accO[nt][0] * INV_N, accO[nt][1] * INV_N);
            *(float2*)&g_attn[(size_t)(i + 8) * 256 + l] =
                make_float2(accO[nt][2] * INV_N, accO[nt][3] * INV_N);
        }
    }
}

// ---------------------------------------------------------------------------
// Kernel 4: oin = u * LN(attn), warp-per-token
// ---------------------------------------------------------------------------
__global__ void oin_kernel() {
    int t = blockIdx.x * 8 + (threadIdx.x >> 5);
    int lane = threadIdx.x & 31;
    const float* row = g_attn + (size_t)t * 256 + lane * 4;
    float4 a0 = *(const float4*)(row);
    float4 a1 = *(const float4*)(row + 128);
    float s = a0.x + a0.y + a0.z + a0.w + a1.x + a1.y + a1.z + a1.w;
    float q = a0.x*a0.x + a0.y*a0.y + a0.z*a0.z + a0.w*a0.w
            + a1.x*a1.x + a1.y*a1.y + a1.z*a1.z + a1.w*a1.w;
    #pragma unroll
    for (int o = 16; o > 0; o >>= 1) {
        s += __shfl_xor_sync(0xffffffffu, s, o);
        q += __shfl_xor_sync(0xffffffffu, q, o);
    }
    float m = s * (1.0f / 256.0f);
    float r = rsqrtf(q * (1.0f / 256.0f) - m * m + EPS);
    const float* up = g_h + (size_t)t * HID + lane * 4;
    float4 u0 = *(const float4*)(up);
    float4 u1 = *(const float4*)(up + 128);
    float* dst = g_oin + (size_t)t * 256 + lane * 4;
    *(float4*)(dst) = make_float4(u0.x * (a0.x - m) * r, u0.y * (a0.y - m) * r,
                                  u0.z * (a0.z - m) * r, u0.w * (a0.w - m) * r);
    *(float4*)(dst + 128) = make_float4(u1.x * (a1.x - m) * r, u1.y * (a1.y - m) * r,
                                        u1.z * (a1.z - m) * r, u1.w * (a1.w - m) * r);
}

// ---------------------------------------------------------------------------
// Kernel 5: out = oin @ o_w^T + o_b + x  -- fp16 mma (unchanged from R8)
// ---------------------------------------------------------------------------
__global__ void gemm_out_h(const float* __restrict__ Wo,
                           const float* __restrict__ bias,
                           const float* __restrict__ x,
                           float* __restrict__ out) {
    __shared__ __align__(16) __half Ah[128 * 40];
    __shared__ __align__(16) __half Wh[64 * 40];
    int tid = threadIdx.x, lane = tid & 31, warp = tid >> 5;
    int wm = warp >> 1, wn = warp & 1;
    int m0 = blockIdx.y * 128, n0 = blockIdx.x * 64;

    float acc[2][4][4];
    #pragma unroll
    for (int a = 0; a < 2; a++)
        #pragma unroll
        for (int b = 0; b < 4; b++)
            #pragma unroll
            for (int c = 0; c < 4; c++) acc[a][b][c] = 0.f;

    int lr = tid >> 1, lk = (tid & 1) << 4;
    int wr = tid >> 2, wc = (tid & 3) << 3;
    const float* Ap = g_oin + (size_t)(m0 + lr) * 256 + lk;
    const float* Wp = Wo + (size_t)(n0 + wr) * 256 + wc;

    unsigned abase = (unsigned)__cvta_generic_to_shared(Ah);
    unsigned wbase = (unsigned)__cvta_generic_to_shared(Wh);
    int a_row = lane & 15, a_col = (lane >> 4) * 8;
    int b_row = ((lane >> 4) * 8) + (lane & 7);
    int b_col = ((lane >> 3) & 1) * 8;

    for (int k0 = 0; k0 < 256; k0 += 32) {
        float4 av[4];
        #pragma unroll
        for (int j = 0; j < 4; j++) av[j] = *(const float4*)(Ap + k0 + 4 * j);
        float4 w0 = *(const float4*)(Wp + k0);
        float4 w1 = *(const float4*)(Wp + k0 + 4);
        __syncthreads();
        *(uint4*)(Ah + lr * 40 + lk) = make_uint4(
            packh2(av[0].x, av[0].y), packh2(av[0].z, av[0].w),
            packh2(av[1].x, av[1].y), packh2(av[1].z, av[1].w));
        *(uint4*)(Ah + lr * 40 + lk + 8) = make_uint4(
            packh2(av[2].x, av[2].y), packh2(av[2].z, av[2].w),
            packh2(av[3].x, av[3].y), packh2(av[3].z, av[3].w));
        *(uint4*)(Wh + wr * 40 + wc) = make_uint4(
            packh2(w0.x, w0.y), packh2(w0.z, w0.w),
            packh2(w1.x, w1.y), packh2(w1.z, w1.w));
        __syncthreads();
        #pragma unroll
        for (int kc = 0; kc < 32; kc += 16) {
            unsigned af[2][4];
            ldsm4(af[0], abase + ((wm * 32 + a_row) * 40 + kc + a_col) * 2);
            ldsm4(af[1], abase + ((wm * 32 + 16 + a_row) * 40 + kc + a_col) * 2);
            #pragma unroll
            for (int n16 = 0; n16 < 2; n16++) {
                unsigned bf[4];
                ldsm4(bf, wbase + ((wn * 32 + n16 * 16 + b_row) * 40 + kc + b_col) * 2);
                mma16(acc[0][n16 * 2],     af[0], bf[0], bf[1]);
                mma16(acc[0][n16 * 2 + 1], af[0], bf[2], bf[3]);
                mma16(acc[1][n16 * 2],     af[1], bf[0], bf[1]);
                mma16(acc[1][n16 * 2 + 1], af[1], bf[2], bf[3]);
            }
        }
    }
    int gid = lane >> 2, tig = lane & 3;
    #pragma unroll
    for (int mm = 0; mm < 2; mm++) {
        #pragma unroll
        for (int nm = 0; nm < 4; nm++) {
            int r = m0 + wm * 32 + mm * 16 + gid;
            int c = n0 + wn * 32 + nm * 8 + 2 * tig;
            float2 xr0 = *(const float2*)&x[(size_t)r * D_DIM + c];
            float2 xr1 = *(const float2*)&x[(size_t)(r + 8) * D_DIM + c];
            float b0 = bias[c], b1 = bias[c + 1];
            *(float2*)&out[(size_t)r * D_DIM + c] =
                make_float2(acc[mm][nm][0] + b0 + xr0.x, acc[mm][nm][1] + b1 + xr0.y);
            *(float2*)&out[(size_t)(r + 8) * D_DIM + c] =
                make_float2(acc[mm][nm][2] + b0 + xr1.x, acc[mm][nm][3] + b1 + xr1.y);
        }
    }
}

// ---------------------------------------------------------------------------
// Launcher
// ---------------------------------------------------------------------------
extern "C" void kernel_launch(void* const* d_in, const int* in_sizes, int n_in,
                              void* d_out, int out_size) {
    const float* x    = (const float*)d_in[0];
    const float* uvqk = (const float*)d_in[1];
    const float* o_w  = (const float*)d_in[2];
    const float* o_b  = (const float*)d_in[3];
    const float* ts_w = (const float*)d_in[4];
    const int*   ts   = (const int*)d_in[5];
    float* out = (float*)d_out;

    ln_x_kernel<<<T_TOK / 8, 256>>>(x);
    gemm_uvqk_h<<<dim3(HID / 64, T_TOK / 128), 256>>>(uvqk);
    attn_mma<<<dim3(100, 4), 256>>>(ts, ts_w);
    oin_kernel<<<T_TOK / 8, 256>>>();
    gemm_out_h<<<dim3(D_DIM / 64, T_TOK / 128), 256>>>(o_w, o_b, x, out);
}

// round 11
// speedup vs baseline: 2.3982x; 1.2053x over previous
#include <cuda_runtime.h>
#include <cuda_bf16.h>
#include <cuda_fp16.h>
#include <math.h>

// ---------------------------------------------------------------------------
// Problem constants
// ---------------------------------------------------------------------------
#define T_TOK   6400
#define D_DIM   512
#define HID     1024
#define N_SEQ   2048
#define EPS     1e-6f
#define INV_N   (1.0f/2048.0f)

__device__ __constant__ int c_off[5] = {0, 2048, 3584, 4608, 6400};
__device__ __constant__ unsigned char c_ord[100][2] = {
 {0,31},{0,30},{0,29},{0,28},
 {0,27},{3,27},{0,26},{3,26},{0,25},{3,25},{0,24},{3,24},
 {0,23},{1,23},{3,23},{0,22},{1,22},{3,22},{0,21},{1,21},{3,21},
 {0,20},{1,20},{3,20},{0,19},{1,19},{3,19},{0,18},{1,18},{3,18},
 {0,17},{1,17},{3,17},{0,16},{1,16},{3,16},
 {0,15},{1,15},{2,15},{3,15},{0,14},{1,14},{2,14},{3,14},
 {0,13},{1,13},{2,13},{3,13},{0,12},{1,12},{2,12},{3,12},
 {0,11},{1,11},{2,11},{3,11},{0,10},{1,10},{2,10},{3,10},
 {0,9},{1,9},{2,9},{3,9},{0,8},{1,8},{2,8},{3,8},
 {0,7},{1,7},{2,7},{3,7},{0,6},{1,6},{2,6},{3,6},
 {0,5},{1,5},{2,5},{3,5},{0,4},{1,4},{2,4},{3,4},
 {0,3},{1,3},{2,3},{3,3},{0,2},{1,2},{2,2},{3,2},
 {0,1},{1,1},{2,1},{3,1},{0,0},{1,0},{2,0},{3,0}};

// ---------------------------------------------------------------------------
// Scratch
// ---------------------------------------------------------------------------
__device__ __half g_xnh [T_TOK * D_DIM];   // LN(x) fp16
__device__ __half g_wh  [D_DIM * HID];     // uvqk fp16
__device__ __half g_owh [D_DIM * 256];     // o_w fp16 [n][k]
__device__ float  g_u   [T_TOK * 256];     // u slice fp32
__device__ __half g_qh  [T_TOK * 256];
__device__ __half g_kh  [T_TOK * 256];
__device__ __half g_vh  [T_TOK * 256];
__device__ float  g_attn[T_TOK * 256];
__device__ __half g_oinh[T_TOK * 256];     // u * LN(attn) fp16

// ---------------------------------------------------------------------------
// helpers
// ---------------------------------------------------------------------------
__device__ __forceinline__ void mma16(float* c, const unsigned* a, unsigned b0, unsigned b1) {
    asm volatile(
      "mma.sync.aligned.m16n8k16.row.col.f32.f16.f16.f32 "
      "{%0,%1,%2,%3}, {%4,%5,%6,%7}, {%8,%9}, {%0,%1,%2,%3};"
      : "+f"(c[0]), "+f"(c[1]), "+f"(c[2]), "+f"(c[3])
      : "r"(a[0]), "r"(a[1]), "r"(a[2]), "r"(a[3]), "r"(b0), "r"(b1));
}
__device__ __forceinline__ void ldsm4(unsigned* r, unsigned addr) {
    asm volatile("ldmatrix.sync.aligned.m8n8.x4.shared.b16 {%0,%1,%2,%3}, [%4];"
        : "=r"(r[0]), "=r"(r[1]), "=r"(r[2]), "=r"(r[3]) : "r"(addr));
}
__device__ __forceinline__ void ldsm4t(unsigned* r, unsigned addr) {
    asm volatile("ldmatrix.sync.aligned.m8n8.x4.trans.shared.b16 {%0,%1,%2,%3}, [%4];"
        : "=r"(r[0]), "=r"(r[1]), "=r"(r[2]), "=r"(r[3]) : "r"(addr));
}
__device__ __forceinline__ void cpa16(unsigned saddr, const void* g) {
    asm volatile("cp.async.ca.shared.global [%0], [%1], 16;" :: "r"(saddr), "l"(g));
}
__device__ __forceinline__ unsigned packh2(float x, float y) {
    __half2 h = __floats2half2_rn(x, y);
    return *(unsigned*)&h;
}
__device__ __forceinline__ float silu_f(float s) {
    return s * __fdividef(1.0f, 1.0f + __expf(-s));
}

// ---------------------------------------------------------------------------
// Kernel 0: one-shot fp16 conversion of uvqk and o_w
// ---------------------------------------------------------------------------
__global__ void convert_w_kernel(const float* __restrict__ uvqk,
                                 const float* __restrict__ ow) {
    int i = blockIdx.x * 1024 + threadIdx.x * 4;
    if (blockIdx.x < 512) {
        float4 v = *(const float4*)(uvqk + i);
        *(uint2*)&g_wh[i] = make_uint2(packh2(v.x, v.y), packh2(v.z, v.w));
    } else {
        int j = i - 512 * 1024;
        float4 v = *(const float4*)(ow + j);
        *(uint2*)&g_owh[j] = make_uint2(packh2(v.x, v.y), packh2(v.z, v.w));
    }
}

// ---------------------------------------------------------------------------
// Kernel 1: LayerNorm over D=512, warp-per-token, fp16 output
// ---------------------------------------------------------------------------
__global__ void ln_x_kernel(const float* __restrict__ x) {
    int t = blockIdx.x * 8 + (threadIdx.x >> 5);
    int lane = threadIdx.x & 31;
    const float* row = x + (size_t)t * D_DIM + lane * 4;
    float4 v[4];
    #pragma unroll
    for (int w = 0; w < 4; w++) v[w] = *(const float4*)(row + w * 128);
    float s = 0.f, q = 0.f;
    #pragma unroll
    for (int w = 0; w < 4; w++) {
        s += v[w].x + v[w].y + v[w].z + v[w].w;
        q += v[w].x*v[w].x + v[w].y*v[w].y + v[w].z*v[w].z + v[w].w*v[w].w;
    }
    #pragma unroll
    for (int o = 16; o > 0; o >>= 1) {
        s += __shfl_xor_sync(0xffffffffu, s, o);
        q += __shfl_xor_sync(0xffffffffu, q, o);
    }
    float m = s * (1.0f / D_DIM);
    float r = rsqrtf(q * (1.0f / D_DIM) - m * m + EPS);
    __half* dst = g_xnh + (size_t)t * D_DIM + lane * 4;
    #pragma unroll
    for (int w = 0; w < 4; w++) {
        *(uint2*)(dst + w * 128) = make_uint2(
            packh2((v[w].x - m) * r, (v[w].y - m) * r),
            packh2((v[w].z - m) * r, (v[w].w - m) * r));
    }
}

// ---------------------------------------------------------------------------
// Kernel 2: h = silu(xnh @ wh)  -- pure fp16, cp.async double-buffered
// BM=128 BN=64 BK=32, 16 k-steps
// ---------------------------------------------------------------------------
__global__ void gemm_uvqk_h() {
    __shared__ __align__(16) __half Ah[2][128 * 40];
    __shared__ __align__(16) __half Bh[2][32 * 72];
    int tid = threadIdx.x, lane = tid & 31, warp = tid >> 5;
    int wm = warp >> 1, wn = warp & 1;
    int m0 = blockIdx.y * 128, n0 = blockIdx.x * 64;

    float acc[2][4][4];
    #pragma unroll
    for (int a = 0; a < 2; a++)
        #pragma unroll
        for (int b = 0; b < 4; b++)
            #pragma unroll
            for (int c = 0; c < 4; c++) acc[a][b][c] = 0.f;

    unsigned abase0 = (unsigned)__cvta_generic_to_shared(Ah[0]);
    unsigned bbase0 = (unsigned)__cvta_generic_to_shared(Bh[0]);
    int a_row = lane & 15, a_col = (lane >> 4) * 8;
    int v_row = (lane & 7) + ((lane >> 3) & 1) * 8;
    int v_col = (lane >> 4) * 8;

    // cp.async thread mapping
    int ar[2], ac[2];
    #pragma unroll
    for (int it = 0; it < 2; it++) {
        int i = tid + it * 256;
        ar[it] = i >> 2; ac[it] = (i & 3) << 3;   // A: 128 rows x 4 chunks
    }
    int br = tid >> 3, bc = (tid & 7) << 3;       // B: 32 rows x 8 chunks

    // prologue: k0 = 0 into buf 0
    #pragma unroll
    for (int it = 0; it < 2; it++)
        cpa16(abase0 + (ar[it] * 40 + ac[it]) * 2,
              g_xnh + (size_t)(m0 + ar[it]) * D_DIM + ac[it]);
    cpa16(bbase0 + (br * 72 + bc) * 2, g_wh + (size_t)br * HID + n0 + bc);
    asm volatile("cp.async.commit_group;");

    for (int ki = 0; ki < 16; ++ki) {
        int buf = ki & 1;
        asm volatile("cp.async.wait_group 0;");
        __syncthreads();
        if (ki < 15) {
            int k1 = (ki + 1) * 32;
            unsigned ab = abase0 + (buf ^ 1) * 128 * 40 * 2;
            unsigned bb = bbase0 + (buf ^ 1) * 32 * 72 * 2;
            #pragma unroll
            for (int it = 0; it < 2; it++)
                cpa16(ab + (ar[it] * 40 + ac[it]) * 2,
                      g_xnh + (size_t)(m0 + ar[it]) * D_DIM + k1 + ac[it]);
            cpa16(bb + (br * 72 + bc) * 2,
                  g_wh + (size_t)(k1 + br) * HID + n0 + bc);
            asm volatile("cp.async.commit_group;");
        }
        unsigned abase = abase0 + buf * 128 * 40 * 2;
        unsigned bbase = bbase0 + buf * 32 * 72 * 2;
        #pragma unroll
        for (int kc = 0; kc < 32; kc += 16) {
            unsigned af[2][4];
            ldsm4(af[0], abase + ((wm * 32 + a_row) * 40 + kc + a_col) * 2);
            ldsm4(af[1], abase + ((wm * 32 + 16 + a_row) * 40 + kc + a_col) * 2);
            #pragma unroll
            for (int n16 = 0; n16 < 2; n16++) {
                unsigned bf[4];
                ldsm4t(bf, bbase + ((kc + v_row) * 72 + wn * 32 + n16 * 16 + v_col) * 2);
                mma16(acc[0][n16 * 2],     af[0], bf[0], bf[1]);
                mma16(acc[0][n16 * 2 + 1], af[0], bf[2], bf[3]);
                mma16(acc[1][n16 * 2],     af[1], bf[0], bf[1]);
                mma16(acc[1][n16 * 2 + 1], af[1], bf[2], bf[3]);
            }
        }
    }
    int gid = lane >> 2, tig = lane & 3;
    int seg = n0 >> 8;                       // 0=u 1=v 2=q 3=k
    __half* segp = (seg == 1) ? g_vh : (seg == 2) ? g_qh : g_kh;
    #pragma unroll
    for (int mm = 0; mm < 2; mm++) {
        #pragma unroll
        for (int nm = 0; nm < 4; nm++) {
            int r = m0 + wm * 32 + mm * 16 + gid;
            int c = (n0 & 255) + wn * 32 + nm * 8 + 2 * tig;
            float s0 = silu_f(acc[mm][nm][0]), s1 = silu_f(acc[mm][nm][1]);
            float s2 = silu_f(acc[mm][nm][2]), s3 = silu_f(acc[mm][nm][3]);
            if (seg == 0) {
                *(float2*)&g_u[(size_t)r * 256 + c] = make_float2(s0, s1);
                *(float2*)&g_u[(size_t)(r + 8) * 256 + c] = make_float2(s2, s3);
            } else {
                *(unsigned*)&segp[(size_t)r * 256 + c] = packh2(s0, s1);
                *(unsigned*)&segp[(size_t)(r + 8) * 256 + c] = packh2(s2, s3);
            }
        }
    }
}

// ---------------------------------------------------------------------------
// Kernel 3: jagged causal attention (unchanged from R10)
// ---------------------------------------------------------------------------
#define HS 72
#define KV_B 9216
#define SM_Q  0
#define SM_K0 9216
#define SM_V0 27648
#define SM_TW 46080
#define SM_TH 46608
#define SM_TQ 46672
#define SM_TK 46928
#define SM_TOT 47440

__global__ void __launch_bounds__(256, 2)
attn_mma(const int* __restrict__ ts, const float* __restrict__ tsw) {
    __shared__ __align__(16) unsigned char smb[SM_TOT];
    __half* Qh = (__half*)(smb + SM_Q);
    float*  red = (float*)smb;
    float*  tw  = (float*)(smb + SM_TW);
    float*  thf = (float*)(smb + SM_TH);
    int*    tqs = (int*)(smb + SM_TQ);
    int*    tkb = (int*)(smb + SM_TK);

    int b  = c_ord[blockIdx.x][0];
    int qt = c_ord[blockIdx.x][1];
    int head = blockIdx.y;
    int tok0 = c_off[b] + qt * 64;

    int tid = threadIdx.x, lane = tid & 31, warp = tid >> 5;
    int wm = warp >> 1, wn = warp & 1;
    int i0 = wm * 16;
    int gid = lane >> 2, tig = lane & 3;

    unsigned qbase  = (unsigned)__cvta_generic_to_shared(smb + SM_Q);
    unsigned kbase0 = (unsigned)__cvta_generic_to_shared(smb + SM_K0);
    unsigned vbase0 = (unsigned)__cvta_generic_to_shared(smb + SM_V0);

    const __half* qb = g_qh + head * 64;
    const __half* kb = g_kh + head * 64;
    const __half* vb = g_vh + head * 64;

    #pragma unroll
    for (int it = 0; it < 2; it++) {
        int i = tid + it * 256;
        int r = i >> 3, c = (i & 7) << 3;
        *(uint4*)(Qh + r * HS + c) =
            *(const uint4*)(qb + (size_t)(tok0 + r) * 256 + c);
    }
    for (int i = tid; i < 129; i += 256) tw[i] = tsw[i];
    if (tid < 64) tqs[tid] = ts[b * N_SEQ + qt * 64 + tid];
    if (tid < 15) {
        if (tid == 0) thf[0] = 0.f;
        else {
            int k = tid;
            int t = (int)(expf((float)k)) - 9;
            if (t < 1) t = 1;
            while (t > 1 && log1pf((float)(t - 1)) >= (float)k) --t;
            while (log1pf((float)t) < (float)k) ++t;
            thf[k] = (float)t;
        }
    }

    {
        int ktok = c_off[b];
        #pragma unroll
        for (int it = 0; it < 2; it++) {
            int i = tid + it * 256;
            int r = i >> 3, c = (i & 7) << 3;
            unsigned soff = (unsigned)((r * HS + c) * 2);
            cpa16(kbase0 + soff, kb + (size_t)(ktok + r) * 256 + c);
            cpa16(vbase0 + soff, vb + (size_t)(ktok + r) * 256 + c);
        }
        asm volatile("cp.async.commit_group;");
        if (tid < 64) tkb[tid] = ts[b * N_SEQ + tid];
    }
    __syncthreads();
    float th[14];
    #pragma unroll
    for (int k = 0; k < 14; k++) th[k] = thf[k + 1];
    int tq0 = tqs[i0 + gid];
    int tq8 = tqs[i0 + gid + 8];

    float accO[8][4];
    #pragma unroll
    for (int t = 0; t < 8; t++)
        #pragma unroll
        for (int c = 0; c < 4; c++) accO[t][c] = 0.f;

    int a_row = lane & 15, a_col = (lane >> 4) * 8;
    int b_row = ((lane >> 4) * 8) + (lane & 7);
    int b_col = ((lane >> 3) & 1) * 8;
    int v_row = (lane & 7) + ((lane >> 3) & 1) * 8;
    int v_col = (lane >> 4) * 8;

    for (int jt = 0; jt <= qt; ++jt) {
        int bbuf = jt & 1;
        asm volatile("cp.async.wait_group 0;");
        __syncthreads();

        if (jt < qt) {
            int ktok = c_off[b] + (jt + 1) * 64;
            unsigned kb1 = kbase0 + (bbuf ^ 1) * KV_B;
            unsigned vb1 = vbase0 + (bbuf ^ 1) * KV_B;
            #pragma unroll
            for (int it = 0; it < 2; it++) {
                int i = tid + it * 256;
                int r = i >> 3, c = (i & 7) << 3;
                unsigned soff = (unsigned)((r * HS + c) * 2);
                cpa16(kb1 + soff, kb + (size_t)(ktok + r) * 256 + c);
                cpa16(vb1 + soff, vb + (size_t)(ktok + r) * 256 + c);
            }
            asm volatile("cp.async.commit_group;");
            if (tid < 64) tkb[(bbuf ^ 1) * 64 + tid] = ts[b * N_SEQ + (jt + 1) * 64 + tid];
        }

        unsigned kbase = kbase0 + bbuf * KV_B;
        unsigned vbase = vbase0 + bbuf * KV_B;
        const int* tks = tkb + bbuf * 64;

        float accS[4][4];
        #pragma unroll
        for (int a = 0; a < 4; a++)
            #pragma unroll
            for (int c = 0; c < 4; c++) accS[a][c] = 0.f;
        #pragma unroll
        for (int kc = 0; kc < 4; kc++) {
            int d0 = kc * 16;
            unsigned af[4];
            ldsm4(af, qbase + ((i0 + a_row) * HS + d0 + a_col) * 2);
            #pragma unroll
            for (int hh = 0; hh < 2; hh++) {
                int j0 = wn * 32 + hh * 16;
                unsigned bf[4];
                ldsm4(bf, kbase + ((j0 + b_row) * HS + d0 + b_col) * 2);
                mma16(accS[hh * 2],     af, bf[0], bf[1]);
                mma16(accS[hh * 2 + 1], af, bf[2], bf[3]);
            }
        }

        bool full = (jt < qt);
        #pragma unroll
        for (int nm = 0; nm < 4; nm++) {
            #pragma unroll
            for (int e = 0; e < 4; e++) {
                int i = i0 + gid + ((e & 2) ? 8 : 0);
                int j = wn * 32 + nm * 8 + tig * 2 + (e & 1);
                float p = 0.f;
                if (full || j <= i) {
                    int tq = (e & 2) ? tq8 : tq0;
                    float fd = fabsf((float)(tq - tks[j]));
                    int bkt = 0;
                    #pragma unroll
                    for (int k = 0; k < 14; k++) bkt += (fd >= th[k]) ? 1 : 0;
                    p = silu_f(accS[nm][e] + tw[bkt]);
                }
                accS[nm][e] = p;
            }
        }

        unsigned pa[2][4];
        #pragma unroll
        for (int kc = 0; kc < 2; kc++) {
            pa[kc][0] = packh2(accS[2*kc][0],     accS[2*kc][1]);
            pa[kc][1] = packh2(accS[2*kc][2],     accS[2*kc][3]);
            pa[kc][2] = packh2(accS[2*kc+1][0],   accS[2*kc+1][1]);
            pa[kc][3] = packh2(accS[2*kc+1][2],   accS[2*kc+1][3]);
        }

        #pragma unroll
        for (int kc = 0; kc < 2; kc++) {
            int jc = wn * 32 + kc * 16;
            #pragma unroll
            for (int lt = 0; lt < 4; lt++) {
                int l0 = lt * 16;
                unsigned bf[4];
                ldsm4t(bf, vbase + ((jc + v_row) * HS + l0 + v_col) * 2);
                mma16(accO[lt * 2],     pa[kc], bf[0], bf[1]);
                mma16(accO[lt * 2 + 1], pa[kc], bf[2], bf[3]);
            }
        }
    }

    __syncthreads();
    if (wn == 1) {
        #pragma unroll
        for (int t = 0; t < 8; t++)
            #pragma unroll
            for (int e = 0; e < 4; e++)
                red[((t * 4 + e) * 4 + wm) * 32 + lane] = accO[t][e];
    }
    __syncthreads();
    if (wn == 0) {
        #pragma unroll
        for (int t = 0; t < 8; t++)
            #pragma unroll
            for (int e = 0; e < 4; e++)
                accO[t][e] += red[((t * 4 + e) * 4 + wm) * 32 + lane];
        #pragma unroll
        for (int nt = 0; nt < 8; nt++) {
            int i = tok0 + i0 + gid;
            int l = head * 64 + nt * 8 + tig * 2;
            *(float2*)&g_attn[(size_t)i * 256 + l] =
                make_float2(accO[nt][0] * INV_N, accO[nt][1] * INV_N);
            *(float2*)&g_attn[(size_t)(i + 8) * 256 + l] =
                make_float2(accO[nt][2] * INV_N, accO[nt][3] * INV_N);
        }
    }
}

// ---------------------------------------------------------------------------
// Kernel 4: oin = u * LN(attn), warp-per-token, fp16 output
// ---------------------------------------------------------------------------
__global__ void oin_kernel() {
    int t = blockIdx.x * 8 + (threadIdx.x >> 5);
    int lane = threadIdx.x & 31;
    const float* row = g_attn + (size_t)t * 256 + lane * 4;
    float4 a0 = *(const float4*)(row);
    float4 a1 = *(const float4*)(row + 128);
    float s = a0.x + a0.y + a0.z + a0.w + a1.x + a1.y + a1.z + a1.w;
    float q = a0.x*a0.x + a0.y*a0.y + a0.z*a0.z + a0.w*a0.w
            + a1.x*a1.x + a1.y*a1.y + a1.z*a1.z + a1.w*a1.w;
    #pragma unroll
    for (int o = 16; o > 0; o >>= 1) {
        s += __shfl_xor_sync(0xffffffffu, s, o);
        q += __shfl_xor_sync(0xffffffffu, q, o);
    }
    float m = s * (1.0f / 256.0f);
    float r = rsqrtf(q * (1.0f / 256.0f) - m * m + EPS);
    const float* up = g_u + (size_t)t * 256 + lane * 4;
    float4 u0 = *(const float4*)(up);
    float4 u1 = *(const float4*)(up + 128);
    __half* dst = g_oinh + (size_t)t * 256 + lane * 4;
    *(uint2*)(dst) = make_uint2(
        packh2(u0.x * (a0.x - m) * r, u0.y * (a0.y - m) * r),
        packh2(u0.z * (a0.z - m) * r, u0.w * (a0.w - m) * r));
    *(uint2*)(dst + 128) = make_uint2(
        packh2(u1.x * (a1.x - m) * r, u1.y * (a1.y - m) * r),
        packh2(u1.z * (a1.z - m) * r, u1.w * (a1.w - m) * r));
}

// ---------------------------------------------------------------------------
// Kernel 5: out = oinh @ owh^T + o_b + x  -- pure fp16, cp.async pipelined
// ---------------------------------------------------------------------------
__global__ void gemm_out_h(const float* __restrict__ bias,
                           const float* __restrict__ x,
                           float* __restrict__ out) {
    __shared__ __align__(16) __half Ah[2][128 * 40];
    __shared__ __align__(16) __half Wh[2][64 * 40];
    int tid = threadIdx.x, lane = tid & 31, warp = tid >> 5;
    int wm = warp >> 1, wn = warp & 1;
    int m0 = blockIdx.y * 128, n0 = blockIdx.x * 64;

    float acc[2][4][4];
    #pragma unroll
    for (int a = 0; a < 2; a++)
        #pragma unroll
        for (int b = 0; b < 4; b++)
            #pragma unroll
            for (int c = 0; c < 4; c++) acc[a][b][c] = 0.f;

    unsigned abase0 = (unsigned)__cvta_generic_to_shared(Ah[0]);
    unsigned wbase0 = (unsigned)__cvta_generic_to_shared(Wh[0]);
    int a_row = lane & 15, a_col = (lane >> 4) * 8;
    int b_row = ((lane >> 4) * 8) + (lane & 7);
    int b_col = ((lane >> 3) & 1) * 8;

    int ar[2], ac[2];
    #pragma unroll
    for (int it = 0; it < 2; it++) {
        int i = tid + it * 256;
        ar[it] = i >> 2; ac[it] = (i & 3) << 3;
    }
    int wr = tid >> 2, wc = (tid & 3) << 3;   // 64 rows x 4 chunks

    #pragma unroll
    for (int it = 0; it < 2; it++)
        cpa16(abase0 + (ar[it] * 40 + ac[it]) * 2,
              g_oinh + (size_t)(m0 + ar[it]) * 256 + ac[it]);
    cpa16(wbase0 + (wr * 40 + wc) * 2, g_owh + (size_t)(n0 + wr) * 256 + wc);
    asm volatile("cp.async.commit_group;");

    for (int ki = 0; ki < 8; ++ki) {
        int buf = ki & 1;
        asm volatile("cp.async.wait_group 0;");
        __syncthreads();
        if (ki < 7) {
            int k1 = (ki + 1) * 32;
            unsigned ab = abase0 + (buf ^ 1) * 128 * 40 * 2;
            unsigned wb = wbase0 + (buf ^ 1) * 64 * 40 * 2;
            #pragma unroll
            for (int it = 0; it < 2; it++)
                cpa16(ab + (ar[it] * 40 + ac[it]) * 2,
                      g_oinh + (size_t)(m0 + ar[it]) * 256 + k1 + ac[it]);
            cpa16(wb + (wr * 40 + wc) * 2,
                  g_owh + (size_t)(n0 + wr) * 256 + k1 + wc);
            asm volatile("cp.async.commit_group;");
        }
        unsigned abase = abase0 + buf * 128 * 40 * 2;
        unsigned wbase = wbase0 + buf * 64 * 40 * 2;
        #pragma unroll
        for (int kc = 0; kc < 32; kc += 16) {
            unsigned af[2][4];
            ldsm4(af[0], abase + ((wm * 32 + a_row) * 40 + kc + a_col) * 2);
            ldsm4(af[1], abase + ((wm * 32 + 16 + a_row) * 40 + kc + a_col) * 2);
            #pragma unroll
            for (int n16 = 0; n16 < 2; n16++) {
                unsigned bf[4];
                ldsm4(bf, wbase + ((wn * 32 + n16 * 16 + b_row) * 40 + kc + b_col) * 2);
                mma16(acc[0][n16 * 2],     af[0], bf[0], bf[1]);
                mma16(acc[0][n16 * 2 + 1], af[0], bf[2], bf[3]);
                mma16(acc[1][n16 * 2],     af[1], bf[0], bf[1]);
                mma16(acc[1][n16 * 2 + 1], af[1], bf[2], bf[3]);
            }
        }
    }
    int gid = lane >> 2, tig = lane & 3;
    #pragma unroll
    for (int mm = 0; mm < 2; mm++) {
        #pragma unroll
        for (int nm = 0; nm < 4; nm++) {
            int r = m0 + wm * 32 + mm * 16 + gid;
            int c = n0 + wn * 32 + nm * 8 + 2 * tig;
            float2 xr0 = *(const float2*)&x[(size_t)r * D_DIM + c];
            float2 xr1 = *(const float2*)&x[(size_t)(r + 8) * D_DIM + c];
            float b0 = bias[c], b1 = bias[c + 1];
            *(float2*)&out[(size_t)r * D_DIM + c] =
                make_float2(acc[mm][nm][0] + b0 + xr0.x, acc[mm][nm][1] + b1 + xr0.y);
            *(float2*)&out[(size_t)(r + 8) * D_DIM + c] =
                make_float2(acc[mm][nm][2] + b0 + xr1.x, acc[mm][nm][3] + b1 + xr1.y);
        }
    }
}

// ---------------------------------------------------------------------------
// Launcher
// ---------------------------------------------------------------------------
extern "C" void kernel_launch(void* const* d_in, const int* in_sizes, int n_in,
                              void* d_out, int out_size) {
    const float* x    = (const float*)d_in[0];
    const float* uvqk = (const float*)d_in[1];
    const float* o_w  = (const float*)d_in[2];
    const float* o_b  = (const float*)d_in[3];
    const float* ts_w = (const float*)d_in[4];
    const int*   ts   = (const int*)d_in[5];
    float* out = (float*)d_out;

    convert_w_kernel<<<640, 256>>>(uvqk, o_w);
    ln_x_kernel<<<T_TOK / 8, 256>>>(x);
    gemm_uvqk_h<<<dim3(HID / 64, T_TOK / 128), 256>>>();
    attn_mma<<<dim3(100, 4), 256>>>(ts, ts_w);
    oin_kernel<<<T_TOK / 8, 256>>>();
    gemm_out_h<<<dim3(D_DIM / 64, T_TOK / 128), 256>>>(o_b, x, out);
}

// round 12
// speedup vs baseline: 2.7726x; 1.1561x over previous
#include <cuda_runtime.h>
#include <cuda_bf16.h>
#include <cuda_fp16.h>
#include <math.h>

// ---------------------------------------------------------------------------
// Problem constants
// ---------------------------------------------------------------------------
#define T_TOK   6400
#define D_DIM   512
#define HID     1024
#define N_SEQ   2048
#define EPS     1e-6f
#define INV_N   (1.0f/2048.0f)

__device__ __constant__ int c_off[5] = {0, 2048, 3584, 4608, 6400};
__device__ __constant__ unsigned char c_ord[100][2] = {
 {0,31},{0,30},{0,29},{0,28},
 {0,27},{3,27},{0,26},{3,26},{0,25},{3,25},{0,24},{3,24},
 {0,23},{1,23},{3,23},{0,22},{1,22},{3,22},{0,21},{1,21},{3,21},
 {0,20},{1,20},{3,20},{0,19},{1,19},{3,19},{0,18},{1,18},{3,18},
 {0,17},{1,17},{3,17},{0,16},{1,16},{3,16},
 {0,15},{1,15},{2,15},{3,15},{0,14},{1,14},{2,14},{3,14},
 {0,13},{1,13},{2,13},{3,13},{0,12},{1,12},{2,12},{3,12},
 {0,11},{1,11},{2,11},{3,11},{0,10},{1,10},{2,10},{3,10},
 {0,9},{1,9},{2,9},{3,9},{0,8},{1,8},{2,8},{3,8},
 {0,7},{1,7},{2,7},{3,7},{0,6},{1,6},{2,6},{3,6},
 {0,5},{1,5},{2,5},{3,5},{0,4},{1,4},{2,4},{3,4},
 {0,3},{1,3},{2,3},{3,3},{0,2},{1,2},{2,2},{3,2},
 {0,1},{1,1},{2,1},{3,1},{0,0},{1,0},{2,0},{3,0}};

// ---------------------------------------------------------------------------
// Scratch
// ---------------------------------------------------------------------------
__device__ __half g_xnh [T_TOK * D_DIM];
__device__ __half g_wh  [D_DIM * HID];
__device__ __half g_owh [D_DIM * 256];
__device__ float  g_u   [T_TOK * 256];
__device__ __half g_qh  [T_TOK * 256];
__device__ __half g_kh  [T_TOK * 256];
__device__ __half g_vh  [T_TOK * 256];
__device__ float  g_attn[T_TOK * 256];
__device__ __half g_oinh[T_TOK * 256];

// ---------------------------------------------------------------------------
// helpers
// ---------------------------------------------------------------------------
__device__ __forceinline__ void mma16(float* c, const unsigned* a, unsigned b0, unsigned b1) {
    asm volatile(
      "mma.sync.aligned.m16n8k16.row.col.f32.f16.f16.f32 "
      "{%0,%1,%2,%3}, {%4,%5,%6,%7}, {%8,%9}, {%0,%1,%2,%3};"
      : "+f"(c[0]), "+f"(c[1]), "+f"(c[2]), "+f"(c[3])
      : "r"(a[0]), "r"(a[1]), "r"(a[2]), "r"(a[3]), "r"(b0), "r"(b1));
}
__device__ __forceinline__ void ldsm4(unsigned* r, unsigned addr) {
    asm volatile("ldmatrix.sync.aligned.m8n8.x4.shared.b16 {%0,%1,%2,%3}, [%4];"
        : "=r"(r[0]), "=r"(r[1]), "=r"(r[2]), "=r"(r[3]) : "r"(addr));
}
__device__ __forceinline__ void ldsm4t(unsigned* r, unsigned addr) {
    asm volatile("ldmatrix.sync.aligned.m8n8.x4.trans.shared.b16 {%0,%1,%2,%3}, [%4];"
        : "=r"(r[0]), "=r"(r[1]), "=r"(r[2]), "=r"(r[3]) : "r"(addr));
}
__device__ __forceinline__ void cpa16(unsigned saddr, const void* g) {
    asm volatile("cp.async.ca.shared.global [%0], [%1], 16;" :: "r"(saddr), "l"(g));
}
__device__ __forceinline__ unsigned packh2(float x, float y) {
    __half2 h = __floats2half2_rn(x, y);
    return *(unsigned*)&h;
}
__device__ __forceinline__ float silu_f(float s) {
    return s * __fdividef(1.0f, 1.0f + __expf(-s));
}
__device__ __forceinline__ float tanh_fast(float x) {
    float t; asm("tanh.approx.f32 %0, %1;" : "=f"(t) : "f"(x)); return t;
}

// ---------------------------------------------------------------------------
// Kernel 0: one-shot fp16 conversion of uvqk and o_w
// ---------------------------------------------------------------------------
__global__ void convert_w_kernel(const float* __restrict__ uvqk,
                                 const float* __restrict__ ow) {
    int i = blockIdx.x * 1024 + threadIdx.x * 4;
    if (blockIdx.x < 512) {
        float4 v = *(const float4*)(uvqk + i);
        *(uint2*)&g_wh[i] = make_uint2(packh2(v.x, v.y), packh2(v.z, v.w));
    } else {
        int j = i - 512 * 1024;
        float4 v = *(const float4*)(ow + j);
        *(uint2*)&g_owh[j] = make_uint2(packh2(v.x, v.y), packh2(v.z, v.w));
    }
}

// ---------------------------------------------------------------------------
// Kernel 1: LayerNorm over D=512, warp-per-token, fp16 output
// ---------------------------------------------------------------------------
__global__ void ln_x_kernel(const float* __restrict__ x) {
    int t = blockIdx.x * 8 + (threadIdx.x >> 5);
    int lane = threadIdx.x & 31;
    const float* row = x + (size_t)t * D_DIM + lane * 4;
    float4 v[4];
    #pragma unroll
    for (int w = 0; w < 4; w++) v[w] = *(const float4*)(row + w * 128);
    float s = 0.f, q = 0.f;
    #pragma unroll
    for (int w = 0; w < 4; w++) {
        s += v[w].x + v[w].y + v[w].z + v[w].w;
        q += v[w].x*v[w].x + v[w].y*v[w].y + v[w].z*v[w].z + v[w].w*v[w].w;
    }
    #pragma unroll
    for (int o = 16; o > 0; o >>= 1) {
        s += __shfl_xor_sync(0xffffffffu, s, o);
        q += __shfl_xor_sync(0xffffffffu, q, o);
    }
    float m = s * (1.0f / D_DIM);
    float r = rsqrtf(q * (1.0f / D_DIM) - m * m + EPS);
    __half* dst = g_xnh + (size_t)t * D_DIM + lane * 4;
    #pragma unroll
    for (int w = 0; w < 4; w++) {
        *(uint2*)(dst + w * 128) = make_uint2(
            packh2((v[w].x - m) * r, (v[w].y - m) * r),
            packh2((v[w].z - m) * r, (v[w].w - m) * r));
    }
}

// ---------------------------------------------------------------------------
// Kernel 2: h = silu(xnh @ wh)  -- pure fp16, cp.async double-buffered
// ---------------------------------------------------------------------------
__global__ void gemm_uvqk_h() {
    __shared__ __align__(16) __half Ah[2][128 * 40];
    __shared__ __align__(16) __half Bh[2][32 * 72];
    int tid = threadIdx.x, lane = tid & 31, warp = tid >> 5;
    int wm = warp >> 1, wn = warp & 1;
    int m0 = blockIdx.y * 128, n0 = blockIdx.x * 64;

    float acc[2][4][4];
    #pragma unroll
    for (int a = 0; a < 2; a++)
        #pragma unroll
        for (int b = 0; b < 4; b++)
            #pragma unroll
            for (int c = 0; c < 4; c++) acc[a][b][c] = 0.f;

    unsigned abase0 = (unsigned)__cvta_generic_to_shared(Ah[0]);
    unsigned bbase0 = (unsigned)__cvta_generic_to_shared(Bh[0]);
    int a_row = lane & 15, a_col = (lane >> 4) * 8;
    int v_row = (lane & 7) + ((lane >> 3) & 1) * 8;
    int v_col = (lane >> 4) * 8;

    int ar[2], ac[2];
    #pragma unroll
    for (int it = 0; it < 2; it++) {
        int i = tid + it * 256;
        ar[it] = i >> 2; ac[it] = (i & 3) << 3;
    }
    int br = tid >> 3, bc = (tid & 7) << 3;

    #pragma unroll
    for (int it = 0; it < 2; it++)
        cpa16(abase0 + (ar[it] * 40 + ac[it]) * 2,
              g_xnh + (size_t)(m0 + ar[it]) * D_DIM + ac[it]);
    cpa16(bbase0 + (br * 72 + bc) * 2, g_wh + (size_t)br * HID + n0 + bc);
    asm volatile("cp.async.commit_group;");

    for (int ki = 0; ki < 16; ++ki) {
        int buf = ki & 1;
        asm volatile("cp.async.wait_group 0;");
        __syncthreads();
        if (ki < 15) {
            int k1 = (ki + 1) * 32;
            unsigned ab = abase0 + (buf ^ 1) * 128 * 40 * 2;
            unsigned bb = bbase0 + (buf ^ 1) * 32 * 72 * 2;
            #pragma unroll
            for (int it = 0; it < 2; it++)
                cpa16(ab + (ar[it] * 40 + ac[it]) * 2,
                      g_xnh + (size_t)(m0 + ar[it]) * D_DIM + k1 + ac[it]);
            cpa16(bb + (br * 72 + bc) * 2,
                  g_wh + (size_t)(k1 + br) * HID + n0 + bc);
            asm volatile("cp.async.commit_group;");
        }
        unsigned abase = abase0 + buf * 128 * 40 * 2;
        unsigned bbase = bbase0 + buf * 32 * 72 * 2;
        #pragma unroll
        for (int kc = 0; kc < 32; kc += 16) {
            unsigned af[2][4];
            ldsm4(af[0], abase + ((wm * 32 + a_row) * 40 + kc + a_col) * 2);
            ldsm4(af[1], abase + ((wm * 32 + 16 + a_row) * 40 + kc + a_col) * 2);
            #pragma unroll
            for (int n16 = 0; n16 < 2; n16++) {
                unsigned bf[4];
                ldsm4t(bf, bbase + ((kc + v_row) * 72 + wn * 32 + n16 * 16 + v_col) * 2);
                mma16(acc[0][n16 * 2],     af[0], bf[0], bf[1]);
                mma16(acc[0][n16 * 2 + 1], af[0], bf[2], bf[3]);
                mma16(acc[1][n16 * 2],     af[1], bf[0], bf[1]);
                mma16(acc[1][n16 * 2 + 1], af[1], bf[2], bf[3]);
            }
        }
    }
    int gid = lane >> 2, tig = lane & 3;
    int seg = n0 >> 8;
    __half* segp = (seg == 1) ? g_vh : (seg == 2) ? g_qh : g_kh;
    #pragma unroll
    for (int mm = 0; mm < 2; mm++) {
        #pragma unroll
        for (int nm = 0; nm < 4; nm++) {
            int r = m0 + wm * 32 + mm * 16 + gid;
            int c = (n0 & 255) + wn * 32 + nm * 8 + 2 * tig;
            float s0 = silu_f(acc[mm][nm][0]), s1 = silu_f(acc[mm][nm][1]);
            float s2 = silu_f(acc[mm][nm][2]), s3 = silu_f(acc[mm][nm][3]);
            if (seg == 0) {
                *(float2*)&g_u[(size_t)r * 256 + c] = make_float2(s0, s1);
                *(float2*)&g_u[(size_t)(r + 8) * 256 + c] = make_float2(s2, s3);
            } else {
                *(unsigned*)&segp[(size_t)r * 256 + c] = packh2(s0, s1);
                *(unsigned*)&segp[(size_t)(r + 8) * 256 + c] = packh2(s2, s3);
            }
        }
    }
}

// ---------------------------------------------------------------------------
// Kernel 3: jagged causal attention
// epilogue: octave-table bucket (exact) + tanh.approx silu
// ---------------------------------------------------------------------------
#define HS 72
#define KV_B 9216
#define SM_Q  0
#define SM_K0 9216
#define SM_V0 27648
#define SM_TW 46080
#define SM_TH 46608
#define SM_TQ 46672
#define SM_TK 46928
#define SM_OCT 47440              // 21 x int2 = 168 B
#define SM_TOT 47616

__global__ void __launch_bounds__(256, 2)
attn_mma(const int* __restrict__ ts, const float* __restrict__ tsw) {
    __shared__ __align__(16) unsigned char smb[SM_TOT];
    __half* Qh = (__half*)(smb + SM_Q);
    float*  red = (float*)smb;
    float*  tw  = (float*)(smb + SM_TW);
    float*  thf = (float*)(smb + SM_TH);
    int*    tqs = (int*)(smb + SM_TQ);
    int*    tkb = (int*)(smb + SM_TK);
    int2*   oct = (int2*)(smb + SM_OCT);

    int b  = c_ord[blockIdx.x][0];
    int qt = c_ord[blockIdx.x][1];
    int head = blockIdx.y;
    int tok0 = c_off[b] + qt * 64;

    int tid = threadIdx.x, lane = tid & 31, warp = tid >> 5;
    int wm = warp >> 1, wn = warp & 1;
    int i0 = wm * 16;
    int gid = lane >> 2, tig = lane & 3;

    unsigned qbase  = (unsigned)__cvta_generic_to_shared(smb + SM_Q);
    unsigned kbase0 = (unsigned)__cvta_generic_to_shared(smb + SM_K0);
    unsigned vbase0 = (unsigned)__cvta_generic_to_shared(smb + SM_V0);

    const __half* qb = g_qh + head * 64;
    const __half* kb = g_kh + head * 64;
    const __half* vb = g_vh + head * 64;

    #pragma unroll
    for (int it = 0; it < 2; it++) {
        int i = tid + it * 256;
        int r = i >> 3, c = (i & 7) << 3;
        *(uint4*)(Qh + r * HS + c) =
            *(const uint4*)(qb + (size_t)(tok0 + r) * 256 + c);
    }
    for (int i = tid; i < 129; i += 256) tw[i] = tsw[i];
    if (tid < 64) tqs[tid] = ts[b * N_SEQ + qt * 64 + tid];
    if (tid < 15) {
        if (tid == 0) thf[0] = 0.f;
        else {
            int k = tid;
            int t = (int)(expf((float)k)) - 9;
            if (t < 1) t = 1;
            while (t > 1 && log1pf((float)(t - 1)) >= (float)k) --t;
            while (log1pf((float)t) < (float)k) ++t;
            thf[k] = (float)t;
        }
    }

    {
        int ktok = c_off[b];
        #pragma unroll
        for (int it = 0; it < 2; it++) {
            int i = tid + it * 256;
            int r = i >> 3, c = (i & 7) << 3;
            unsigned soff = (unsigned)((r * HS + c) * 2);
            cpa16(kbase0 + soff, kb + (size_t)(ktok + r) * 256 + c);
            cpa16(vbase0 + soff, vb + (size_t)(ktok + r) * 256 + c);
        }
        asm volatile("cp.async.commit_group;");
        if (tid < 64) tkb[tid] = ts[b * N_SEQ + tid];
    }
    __syncthreads();

    // Build octave table: for x = d+1 with exponent e, bucket(d) = base[e] + (d >= thr[e]).
    if (tid < 21) {
        int e = tid;
        float dlo = (float)((1u << e) - 1u);   // smallest d in this octave
        int base = 0;
        #pragma unroll
        for (int k = 1; k <= 14; k++) base += (dlo >= thf[k]) ? 1 : 0;
        float thr = (base < 14) ? thf[base + 1] : 3.0e8f;
        oct[e] = make_int2(base, __float_as_int(thr));
    }
    __syncthreads();

    int tq0 = tqs[i0 + gid];
    int tq8 = tqs[i0 + gid + 8];

    float accO[8][4];
    #pragma unroll
    for (int t = 0; t < 8; t++)
        #pragma unroll
        for (int c = 0; c < 4; c++) accO[t][c] = 0.f;

    int a_row = lane & 15, a_col = (lane >> 4) * 8;
    int b_row = ((lane >> 4) * 8) + (lane & 7);
    int b_col = ((lane >> 3) & 1) * 8;
    int v_row = (lane & 7) + ((lane >> 3) & 1) * 8;
    int v_col = (lane >> 4) * 8;

    for (int jt = 0; jt <= qt; ++jt) {
        int bbuf = jt & 1;
        asm volatile("cp.async.wait_group 0;");
        __syncthreads();

        if (jt < qt) {
            int ktok = c_off[b] + (jt + 1) * 64;
            unsigned kb1 = kbase0 + (bbuf ^ 1) * KV_B;
            unsigned vb1 = vbase0 + (bbuf ^ 1) * KV_B;
            #pragma unroll
            for (int it = 0; it < 2; it++) {
                int i = tid + it * 256;
                int r = i >> 3, c = (i & 7) << 3;
                unsigned soff = (unsigned)((r * HS + c) * 2);
                cpa16(kb1 + soff, kb + (size_t)(ktok + r) * 256 + c);
                cpa16(vb1 + soff, vb + (size_t)(ktok + r) * 256 + c);
            }
            asm volatile("cp.async.commit_group;");
            if (tid < 64) tkb[(bbuf ^ 1) * 64 + tid] = ts[b * N_SEQ + (jt + 1) * 64 + tid];
        }

        unsigned kbase = kbase0 + bbuf * KV_B;
        unsigned vbase = vbase0 + bbuf * KV_B;
        const int* tks = tkb + bbuf * 64;

        float accS[4][4];
        #pragma unroll
        for (int a = 0; a < 4; a++)
            #pragma unroll
            for (int c = 0; c < 4; c++) accS[a][c] = 0.f;
        #pragma unroll
        for (int kc = 0; kc < 4; kc++) {
            int d0 = kc * 16;
            unsigned af[4];
            ldsm4(af, qbase + ((i0 + a_row) * HS + d0 + a_col) * 2);
            #pragma unroll
            for (int hh = 0; hh < 2; hh++) {
                int j0 = wn * 32 + hh * 16;
                unsigned bf[4];
                ldsm4(bf, kbase + ((j0 + b_row) * HS + d0 + b_col) * 2);
                mma16(accS[hh * 2],     af, bf[0], bf[1]);
                mma16(accS[hh * 2 + 1], af, bf[2], bf[3]);
            }
        }

        // epilogue: bias (octave bucket) + silu (tanh) + causal
        bool full = (jt < qt);
        #pragma unroll
        for (int nm = 0; nm < 4; nm++) {
            #pragma unroll
            for (int e = 0; e < 4; e++) {
                int i = i0 + gid + ((e & 2) ? 8 : 0);
                int j = wn * 32 + nm * 8 + tig * 2 + (e & 1);
                float p = 0.f;
                if (full || j <= i) {
                    int tq = (e & 2) ? tq8 : tq0;
                    int d = tq - tks[j];
                    d = (d < 0) ? -d : d;
                    int ex = 31 - __clz(d + 1);
                    int2 ob = oct[ex];
                    int bkt = ob.x + (((float)d >= __int_as_float(ob.y)) ? 1 : 0);
                    float s = accS[nm][e] + tw[bkt];
                    p = s * (0.5f * tanh_fast(s * 0.5f) + 0.5f);
                }
                accS[nm][e] = p;
            }
        }

        unsigned pa[2][4];
        #pragma unroll
        for (int kc = 0; kc < 2; kc++) {
            pa[kc][0] = packh2(accS[2*kc][0],     accS[2*kc][1]);
            pa[kc][1] = packh2(accS[2*kc][2],     accS[2*kc][3]);
            pa[kc][2] = packh2(accS[2*kc+1][0],   accS[2*kc+1][1]);
            pa[kc][3] = packh2(accS[2*kc+1][2],   accS[2*kc+1][3]);
        }

        #pragma unroll
        for (int kc = 0; kc < 2; kc++) {
            int jc = wn * 32 + kc * 16;
            #pragma unroll
            for (int lt = 0; lt < 4; lt++) {
                int l0 = lt * 16;
                unsigned bf[4];
                ldsm4t(bf, vbase + ((jc + v_row) * HS + l0 + v_col) * 2);
                mma16(accO[lt * 2],     pa[kc], bf[0], bf[1]);
                mma16(accO[lt * 2 + 1], pa[kc], bf[2], bf[3]);
            }
        }
    }

    __syncthreads();
    if (wn == 1) {
        #pragma unroll
        for (int t = 0; t < 8; t++)
            #pragma unroll
            for (int e = 0; e < 4; e++)
                red[((t * 4 + e) * 4 + wm) * 32 + lane] = accO[t][e];
    }
    __syncthreads();
    if (wn == 0) {
        #pragma unroll
        for (int t = 0; t < 8; t++)
            #pragma unroll
            for (int e = 0; e < 4; e++)
                accO[t][e] += red[((t * 4 + e) * 4 + wm) * 32 + lane];
        #pragma unroll
        for (int nt = 0; nt < 8; nt++) {
            int i = tok0 + i0 + gid;
            int l = head * 64 + nt * 8 + tig * 2;
            *(float2*)&g_attn[(size_t)i * 256 + l] =
                make_float2(accO[nt][0] * INV_N, accO[nt][1] * INV_N);
            *(float2*)&g_attn[(size_t)(i + 8) * 256 + l] =
                make_float2(accO[nt][2] * INV_N, accO[nt][3] * INV_N);
        }
    }
}

// ---------------------------------------------------------------------------
// Kernel 4: oin = u * LN(attn), warp-per-token, fp16 output
// ---------------------------------------------------------------------------
__global__ void oin_kernel() {
    int t = blockIdx.x * 8 + (threadIdx.x >> 5);
    int lane = threadIdx.x & 31;
    const float* row = g_attn + (size_t)t * 256 + lane * 4;
    float4 a0 = *(const float4*)(row);
    float4 a1 = *(const float4*)(row + 128);
    float s = a0.x + a0.y + a0.z + a0.w + a1.x + a1.y + a1.z + a1.w;
    float q = a0.x*a0.x + a0.y*a0.y + a0.z*a0.z + a0.w*a0.w
            + a1.x*a1.x + a1.y*a1.y + a1.z*a1.z + a1.w*a1.w;
    #pragma unroll
    for (int o = 16; o > 0; o >>= 1) {
        s += __shfl_xor_sync(0xffffffffu, s, o);
        q += __shfl_xor_sync(0xffffffffu, q, o);
    }
    float m = s * (1.0f / 256.0f);
    float r = rsqrtf(q * (1.0f / 256.0f) - m * m + EPS);
    const float* up = g_u + (size_t)t * 256 + lane * 4;
    float4 u0 = *(const float4*)(up);
    float4 u1 = *(const float4*)(up + 128);
    __half* dst = g_oinh + (size_t)t * 256 + lane * 4;
    *(uint2*)(dst) = make_uint2(
        packh2(u0.x * (a0.x - m) * r, u0.y * (a0.y - m) * r),
        packh2(u0.z * (a0.z - m) * r, u0.w * (a0.w - m) * r));
    *(uint2*)(dst + 128) = make_uint2(
        packh2(u1.x * (a1.x - m) * r, u1.y * (a1.y - m) * r),
        packh2(u1.z * (a1.z - m) * r, u1.w * (a1.w - m) * r));
}

// ---------------------------------------------------------------------------
// Kernel 5: out = oinh @ owh^T + o_b + x  -- pure fp16, cp.async pipelined
// ---------------------------------------------------------------------------
__global__ void gemm_out_h(const float* __restrict__ bias,
                           const float* __restrict__ x,
                           float* __restrict__ out) {
    __shared__ __align__(16) __half Ah[2][128 * 40];
    __shared__ __align__(16) __half Wh[2][64 * 40];
    int tid = threadIdx.x, lane = tid & 31, warp = tid >> 5;
    int wm = warp >> 1, wn = warp & 1;
    int m0 = blockIdx.y * 128, n0 = blockIdx.x * 64;

    float acc[2][4][4];
    #pragma unroll
    for (int a = 0; a < 2; a++)
        #pragma unroll
        for (int b = 0; b < 4; b++)
            #pragma unroll
            for (int c = 0; c < 4; c++) acc[a][b][c] = 0.f;

    unsigned abase0 = (unsigned)__cvta_generic_to_shared(Ah[0]);
    unsigned wbase0 = (unsigned)__cvta_generic_to_shared(Wh[0]);
    int a_row = lane & 15, a_col = (lane >> 4) * 8;
    int b_row = ((lane >> 4) * 8) + (lane & 7);
    int b_col = ((lane >> 3) & 1) * 8;

    int ar[2], ac[2];
    #pragma unroll
    for (int it = 0; it < 2; it++) {
        int i = tid + it * 256;
        ar[it] = i >> 2; ac[it] = (i & 3) << 3;
    }
    int wr = tid >> 2, wc = (tid & 3) << 3;

    #pragma unroll
    for (int it = 0; it < 2; it++)
        cpa16(abase0 + (ar[it] * 40 + ac[it]) * 2,
              g_oinh + (size_t)(m0 + ar[it]) * 256 + ac[it]);
    cpa16(wbase0 + (wr * 40 + wc) * 2, g_owh + (size_t)(n0 + wr) * 256 + wc);
    asm volatile("cp.async.commit_group;");

    for (int ki = 0; ki < 8; ++ki) {
        int buf = ki & 1;
        asm volatile("cp.async.wait_group 0;");
        __syncthreads();
        if (ki < 7) {
            int k1 = (ki + 1) * 32;
            unsigned ab = abase0 + (buf ^ 1) * 128 * 40 * 2;
            unsigned wb = wbase0 + (buf ^ 1) * 64 * 40 * 2;
            #pragma unroll
            for (int it = 0; it < 2; it++)
                cpa16(ab + (ar[it] * 40 + ac[it]) * 2,
                      g_oinh + (size_t)(m0 + ar[it]) * 256 + k1 + ac[it]);
            cpa16(wb + (wr * 40 + wc) * 2,
                  g_owh + (size_t)(n0 + wr) * 256 + k1 + wc);
            asm volatile("cp.async.commit_group;");
        }
        unsigned abase = abase0 + buf * 128 * 40 * 2;
        unsigned wbase = wbase0 + buf * 64 * 40 * 2;
        #pragma unroll
        for (int kc = 0; kc < 32; kc += 16) {
            unsigned af[2][4];
            ldsm4(af[0], abase + ((wm * 32 + a_row) * 40 + kc + a_col) * 2);
            ldsm4(af[1], abase + ((wm * 32 + 16 + a_row) * 40 + kc + a_col) * 2);
            #pragma unroll
            for (int n16 = 0; n16 < 2; n16++) {
                unsigned bf[4];
                ldsm4(bf, wbase + ((wn * 32 + n16 * 16 + b_row) * 40 + kc + b_col) * 2);
                mma16(acc[0][n16 * 2],     af[0], bf[0], bf[1]);
                mma16(acc[0][n16 * 2 + 1], af[0], bf[2], bf[3]);
                mma16(acc[1][n16 * 2],     af[1], bf[0], bf[1]);
                mma16(acc[1][n16 * 2 + 1], af[1], bf[2], bf[3]);
            }
        }
    }
    int gid = lane >> 2, tig = lane & 3;
    #pragma unroll
    for (int mm = 0; mm < 2; mm++) {
        #pragma unroll
        for (int nm = 0; nm < 4; nm++) {
            int r = m0 + wm * 32 + mm * 16 + gid;
            int c = n0 + wn * 32 + nm * 8 + 2 * tig;
            float2 xr0 = *(const float2*)&x[(size_t)r * D_DIM + c];
            float2 xr1 = *(const float2*)&x[(size_t)(r + 8) * D_DIM + c];
            float b0 = bias[c], b1 = bias[c + 1];
            *(float2*)&out[(size_t)r * D_DIM + c] =
                make_float2(acc[mm][nm][0] + b0 + xr0.x, acc[mm][nm][1] + b1 + xr0.y);
            *(float2*)&out[(size_t)(r + 8) * D_DIM + c] =
                make_float2(acc[mm][nm][2] + b0 + xr1.x, acc[mm][nm][3] + b1 + xr1.y);
        }
    }
}

// ---------------------------------------------------------------------------
// Launcher
// ---------------------------------------------------------------------------
extern "C" void kernel_launch(void* const* d_in, const int* in_sizes, int n_in,
                              void* d_out, int out_size) {
    const float* x    = (const float*)d_in[0];
    const float* uvqk = (const float*)d_in[1];
    const float* o_w  = (const float*)d_in[2];
    const float* o_b  = (const float*)d_in[3];
    const float* ts_w = (const float*)d_in[4];
    const int*   ts   = (const int*)d_in[5];
    float* out = (float*)d_out;

    convert_w_kernel<<<640, 256>>>(uvqk, o_w);
    ln_x_kernel<<<T_TOK / 8, 256>>>(x);
    gemm_uvqk_h<<<dim3(HID / 64, T_TOK / 128), 256>>>();
    attn_mma<<<dim3(100, 4), 256>>>(ts, ts_w);
    oin_kernel<<<T_TOK / 8, 256>>>();
    gemm_out_h<<<dim3(D_DIM / 64, T_TOK / 128), 256>>>(o_b, x, out);
}